// round 2
// baseline (speedup 1.0000x reference)
#include <cuda_runtime.h>
#include <cuda_bf16.h>
#include <math.h>

#define SS 256       // sequence
#define CC 128       // channels
#define NH 4
#define HD 32
#define MTOT (SS*SS) // 65536
#define ATT_SCALE 0.17677669529663687f  // 1/sqrt(32)
#define LN_EPS 1e-5f

// ---------------- scratch (no allocation allowed; single big __device__ blob) ---
// layout (floats):
//   z   : [0,            8388608)
//   qt  : [8388608,     16777216)   transposed: row = j*S + i
//   kt  : [16777216,    25165824)
//   vt  : [25165824,    33554432)
//   gt  : [33554432,    41943040)
//   og  : [41943040,    50331648)   gated attention output, row = j*S + i
//   bias: [50331648,    50593792)   [n][i][k]  (4 * 65536)
__device__ float g_scratch[50331648 + NH*MTOT];

// ---------------- LayerNorm: one warp per row of 128 channels -------------------
__global__ void ln_kernel(const float* __restrict__ x, const float* __restrict__ gamma,
                          const float* __restrict__ beta, float* __restrict__ z) {
    int warp = blockIdx.x * 8 + (threadIdx.x >> 5);
    int lane = threadIdx.x & 31;
    if (warp >= MTOT) return;
    const float4 v = ((const float4*)(x + (size_t)warp * CC))[lane];
    float s  = v.x + v.y + v.z + v.w;
    float sq = v.x*v.x + v.y*v.y + v.z*v.z + v.w*v.w;
    #pragma unroll
    for (int off = 16; off; off >>= 1) {
        s  += __shfl_xor_sync(0xffffffffu, s,  off);
        sq += __shfl_xor_sync(0xffffffffu, sq, off);
    }
    float mu  = s * (1.0f / CC);
    float var = sq * (1.0f / CC) - mu * mu;
    float rs  = rsqrtf(var + LN_EPS);
    const float4 g4 = ((const float4*)gamma)[lane];
    const float4 b4 = ((const float4*)beta)[lane];
    float4 o;
    o.x = (v.x - mu) * rs * g4.x + b4.x;
    o.y = (v.y - mu) * rs * g4.y + b4.y;
    o.z = (v.z - mu) * rs * g4.z + b4.z;
    o.w = (v.w - mu) * rs * g4.w + b4.w;
    ((float4*)(z + (size_t)warp * CC))[lane] = o;
}

// ---------------- GEMM: [M=65536,K=128] x [128,128] (+bias) (+sigmoid) ---------
// Always writes with transposed spatial index: input row R -> output row
// (R % S)*S + R/S. (Works both for i*S+j -> j*S+i and back.)
// Block: 64 rows x 128 cols, 256 threads, 4x8 micro-tile, K split in 2 chunks.
template<int EPI>  // 0 = plain (+bias if non-null), 1 = sigmoid(acc + bias)
__global__ void gemm128_kernel(const float* __restrict__ A, const float* __restrict__ W,
                               const float* __restrict__ bias, float* __restrict__ out) {
    __shared__ float As[64 * 64];
    __shared__ float Bs[64 * 128];
    const int t = threadIdx.x;
    const int row0 = blockIdx.x * 64;
    const int tx = t & 15, ty = t >> 4;

    float acc[4][8];
    #pragma unroll
    for (int r = 0; r < 4; r++)
        #pragma unroll
        for (int c = 0; c < 8; c++) acc[r][c] = 0.f;

    for (int kc = 0; kc < 2; kc++) {
        if (kc) __syncthreads();
        // A chunk: 64 rows x 64 k  (1024 float4)
        #pragma unroll
        for (int i = 0; i < 4; i++) {
            int id = t + i * 256;
            int r = id >> 4, c4 = id & 15;
            ((float4*)As)[id] =
                ((const float4*)(A + (size_t)(row0 + r) * CC + kc * 64))[c4];
        }
        // W chunk: 64 k x 128 n (2048 float4)
        #pragma unroll
        for (int i = 0; i < 8; i++) {
            int id = t + i * 256;
            int r = id >> 5, c4 = id & 31;
            ((float4*)Bs)[id] = ((const float4*)W)[(kc * 64 + r) * 32 + c4];
        }
        __syncthreads();
        #pragma unroll 16
        for (int k = 0; k < 64; k++) {
            float a[4];
            #pragma unroll
            for (int rr = 0; rr < 4; rr++) a[rr] = As[(ty * 4 + rr) * 64 + k];
            float4 b0 = ((const float4*)Bs)[k * 32 + tx * 2];
            float4 b1 = ((const float4*)Bs)[k * 32 + tx * 2 + 1];
            float b[8] = {b0.x, b0.y, b0.z, b0.w, b1.x, b1.y, b1.z, b1.w};
            #pragma unroll
            for (int rr = 0; rr < 4; rr++)
                #pragma unroll
                for (int cc = 0; cc < 8; cc++)
                    acc[rr][cc] += a[rr] * b[cc];
        }
    }

    float bv[8] = {0, 0, 0, 0, 0, 0, 0, 0};
    if (bias) {
        float4 q0 = ((const float4*)bias)[tx * 2];
        float4 q1 = ((const float4*)bias)[tx * 2 + 1];
        bv[0]=q0.x; bv[1]=q0.y; bv[2]=q0.z; bv[3]=q0.w;
        bv[4]=q1.x; bv[5]=q1.y; bv[6]=q1.z; bv[7]=q1.w;
    }
    #pragma unroll
    for (int rr = 0; rr < 4; rr++) {
        int R = row0 + ty * 4 + rr;
        int orow = (R & (SS - 1)) * SS + (R >> 8);
        float* dst = out + (size_t)orow * CC + tx * 8;
        float vals[8];
        #pragma unroll
        for (int cc = 0; cc < 8; cc++) {
            float v = acc[rr][cc] + bv[cc];
            if (EPI == 1) v = 1.0f / (1.0f + __expf(-v));
            vals[cc] = v;
        }
        ((float4*)dst)[0] = make_float4(vals[0], vals[1], vals[2], vals[3]);
        ((float4*)dst)[1] = make_float4(vals[4], vals[5], vals[6], vals[7]);
    }
}

// ---------------- attention bias projection: z @ Wb -> bias[n][i][k] -----------
__global__ void projb_kernel(const float* __restrict__ z, const float* __restrict__ Wb,
                             float* __restrict__ bias) {
    int warp = blockIdx.x * 8 + (threadIdx.x >> 5);
    int lane = threadIdx.x & 31;
    if (warp >= MTOT) return;
    const float4 v = ((const float4*)(z + (size_t)warp * CC))[lane];
    float p0 = 0, p1 = 0, p2 = 0, p3 = 0;
    const float zc[4] = {v.x, v.y, v.z, v.w};
    #pragma unroll
    for (int q = 0; q < 4; q++) {
        int c = lane * 4 + q;
        p0 += zc[q] * Wb[c * 4 + 0];
        p1 += zc[q] * Wb[c * 4 + 1];
        p2 += zc[q] * Wb[c * 4 + 2];
        p3 += zc[q] * Wb[c * 4 + 3];
    }
    #pragma unroll
    for (int off = 16; off; off >>= 1) {
        p0 += __shfl_xor_sync(0xffffffffu, p0, off);
        p1 += __shfl_xor_sync(0xffffffffu, p1, off);
        p2 += __shfl_xor_sync(0xffffffffu, p2, off);
        p3 += __shfl_xor_sync(0xffffffffu, p3, off);
    }
    if (lane == 0) {
        bias[0 * MTOT + warp] = p0;
        bias[1 * MTOT + warp] = p1;
        bias[2 * MTOT + warp] = p2;
        bias[3 * MTOT + warp] = p3;
    }
}

// ---------------- attention: one block per (column j, head n) ------------------
// flash-style online softmax over k; Q row + accumulator in registers.
__global__ void attn_kernel(const float* __restrict__ qt, const float* __restrict__ kt,
                            const float* __restrict__ vt, const float* __restrict__ gt,
                            const float* __restrict__ bias, float* __restrict__ og) {
    const int j = blockIdx.x;
    const int n = blockIdx.y;
    __shared__ float Ks[128 * 32];
    __shared__ float Vs[128 * 32];
    const int t = threadIdx.x;  // == query row i

    float qreg[32];
    {
        const float4* qp = (const float4*)(qt + (size_t)(j * SS + t) * CC + n * HD);
        #pragma unroll
        for (int i = 0; i < 8; i++) {
            float4 q4 = qp[i];
            qreg[4*i] = q4.x; qreg[4*i+1] = q4.y; qreg[4*i+2] = q4.z; qreg[4*i+3] = q4.w;
        }
    }
    const float* brow = bias + (size_t)n * MTOT + (size_t)t * SS;

    float m = -1e30f, l = 0.f;
    float o[32];
    #pragma unroll
    for (int d = 0; d < 32; d++) o[d] = 0.f;

    for (int kc = 0; kc < 2; kc++) {
        __syncthreads();
        #pragma unroll
        for (int i = 0; i < 4; i++) {
            int id = t + i * 256;         // float4 id in [0,1024)
            int row = id >> 3, c4 = id & 7;
            size_t src = (size_t)(j * SS + kc * 128 + row) * CC + n * HD + c4 * 4;
            ((float4*)Ks)[id] = *(const float4*)(kt + src);
            ((float4*)Vs)[id] = *(const float4*)(vt + src);
        }
        __syncthreads();
        #pragma unroll 4
        for (int k = 0; k < 128; k++) {
            float s = 0.f;
            #pragma unroll
            for (int d = 0; d < 32; d++) s += qreg[d] * Ks[k * 32 + d];
            s = s * ATT_SCALE + __ldg(brow + kc * 128 + k);
            float mn = fmaxf(m, s);
            float al = __expf(m - mn);
            float p  = __expf(s - mn);
            l = l * al + p;
            #pragma unroll
            for (int d = 0; d < 32; d++) o[d] = o[d] * al + p * Vs[k * 32 + d];
            m = mn;
        }
    }

    float inv = 1.f / l;
    const float4* gp = (const float4*)(gt + (size_t)(j * SS + t) * CC + n * HD);
    float4* op = (float4*)(og + (size_t)(j * SS + t) * CC + n * HD);
    #pragma unroll
    for (int i = 0; i < 8; i++) {
        float4 g4 = gp[i];
        float4 r;
        r.x = o[4*i]   * inv * g4.x;
        r.y = o[4*i+1] * inv * g4.y;
        r.z = o[4*i+2] * inv * g4.z;
        r.w = o[4*i+3] * inv * g4.w;
        op[i] = r;
    }
}

// ---------------- launch -------------------------------------------------------
extern "C" void kernel_launch(void* const* d_in, const int* in_sizes, int n_in,
                              void* d_out, int out_size) {
    const float* pair  = (const float*)d_in[0];
    const float* gamma = (const float*)d_in[1];
    const float* beta  = (const float*)d_in[2];
    const float* Wq    = (const float*)d_in[3];
    const float* Wk    = (const float*)d_in[4];
    const float* Wv    = (const float*)d_in[5];
    const float* Wb    = (const float*)d_in[6];
    const float* Wg    = (const float*)d_in[7];
    const float* bg    = (const float*)d_in[8];
    const float* Wo    = (const float*)d_in[9];
    const float* bo    = (const float*)d_in[10];
    float* out = (float*)d_out;

    float* base = nullptr;
    cudaGetSymbolAddress((void**)&base, g_scratch);
    float* z    = base;
    float* qt   = base + 1 * 8388608;
    float* kt   = base + 2 * 8388608;
    float* vt   = base + 3 * 8388608;
    float* gt   = base + 4 * 8388608;
    float* og   = base + 5 * 8388608;
    float* bias = base + 6 * 8388608;

    ln_kernel<<<MTOT / 8, 256>>>(pair, gamma, beta, z);

    gemm128_kernel<0><<<MTOT / 64, 256>>>(z, Wq, nullptr, qt);
    gemm128_kernel<0><<<MTOT / 64, 256>>>(z, Wk, nullptr, kt);
    gemm128_kernel<0><<<MTOT / 64, 256>>>(z, Wv, nullptr, vt);
    gemm128_kernel<1><<<MTOT / 64, 256>>>(z, Wg, bg, gt);
    projb_kernel<<<MTOT / 8, 256>>>(z, Wb, bias);

    attn_kernel<<<dim3(SS, NH), 256>>>(qt, kt, vt, gt, bias, og);

    gemm128_kernel<0><<<MTOT / 64, 256>>>(og, Wo, bo, out);
}

// round 3
// speedup vs baseline: 2.2230x; 2.2230x over previous
#include <cuda_runtime.h>
#include <cuda_bf16.h>
#include <math.h>

#define SS 256       // sequence
#define CC 128       // channels
#define NH 4
#define HD 32
#define MTOT (SS*SS) // 65536
#define ATT_SCALE 0.17677669529663687f  // 1/sqrt(32)
#define LN_EPS 1e-5f

// ---------------- scratch (no allocation allowed; single big __device__ blob) ---
// layout (floats):
//   z   : [0,            8388608)
//   qt  : [8388608,     16777216)   transposed: row = j*S + i
//   kt  : [16777216,    25165824)
//   vt  : [25165824,    33554432)
//   gt  : [33554432,    41943040)
//   og  : [41943040,    50331648)   gated attention output, row = j*S + i
//   bias_t: [50331648, +4*65536)    [n][k][i]   (transposed for coalesced reads)
__device__ float g_scratch[50331648 + NH*MTOT];

// ---------------- LayerNorm: one warp per row of 128 channels -------------------
__global__ void ln_kernel(const float* __restrict__ x, const float* __restrict__ gamma,
                          const float* __restrict__ beta, float* __restrict__ z) {
    int warp = blockIdx.x * 8 + (threadIdx.x >> 5);
    int lane = threadIdx.x & 31;
    if (warp >= MTOT) return;
    const float4 v = ((const float4*)(x + (size_t)warp * CC))[lane];
    float s  = v.x + v.y + v.z + v.w;
    float sq = v.x*v.x + v.y*v.y + v.z*v.z + v.w*v.w;
    #pragma unroll
    for (int off = 16; off; off >>= 1) {
        s  += __shfl_xor_sync(0xffffffffu, s,  off);
        sq += __shfl_xor_sync(0xffffffffu, sq, off);
    }
    float mu  = s * (1.0f / CC);
    float var = sq * (1.0f / CC) - mu * mu;
    float rs  = rsqrtf(var + LN_EPS);
    const float4 g4 = ((const float4*)gamma)[lane];
    const float4 b4 = ((const float4*)beta)[lane];
    float4 o;
    o.x = (v.x - mu) * rs * g4.x + b4.x;
    o.y = (v.y - mu) * rs * g4.y + b4.y;
    o.z = (v.z - mu) * rs * g4.z + b4.z;
    o.w = (v.w - mu) * rs * g4.w + b4.w;
    ((float4*)(z + (size_t)warp * CC))[lane] = o;
}

// ---------------- GEMM: [M=65536,K=128] x [128,128] (+bias) (+sigmoid) ---------
// 128x128 block tile, 256 threads, 8x8 microtile (split 4+4 in both dims for
// conflict-free float4 smem reads). A staged transposed in smem (pad 132).
// Writes with transposed spatial index: input row R -> (R % S)*S + R/S.
template<int EPI>  // 0 = plain (+bias if non-null), 1 = sigmoid(acc + bias)
__global__ void __launch_bounds__(256)
gemm128_kernel(const float* __restrict__ A, const float* __restrict__ W,
               const float* __restrict__ bias, float* __restrict__ out) {
    __shared__ float As[16 * 132];   // As[k][m], padded stride 132
    __shared__ float Bs[16 * 128];   // Bs[k][n]
    const int t = threadIdx.x;
    const int row0 = blockIdx.x * 128;
    const int tx = t & 15, ty = t >> 4;

    float acc[8][8];
    #pragma unroll
    for (int r = 0; r < 8; r++)
        #pragma unroll
        for (int c = 0; c < 8; c++) acc[r][c] = 0.f;

    const float4* As4 = (const float4*)As;
    const float4* Bs4 = (const float4*)Bs;

    for (int kc = 0; kc < 8; kc++) {
        if (kc) __syncthreads();
        // A chunk: 128 rows x 16 k -> transposed store into As[k][m]
        #pragma unroll
        for (int i = 0; i < 2; i++) {
            int id = t + i * 256;           // 0..511
            int r = id >> 2, c4 = id & 3;   // row, k-float4
            float4 av = ((const float4*)A)[(size_t)(row0 + r) * 32 + kc * 4 + c4];
            As[(c4 * 4 + 0) * 132 + r] = av.x;
            As[(c4 * 4 + 1) * 132 + r] = av.y;
            As[(c4 * 4 + 2) * 132 + r] = av.z;
            As[(c4 * 4 + 3) * 132 + r] = av.w;
        }
        // W chunk: 16 k x 128 n
        #pragma unroll
        for (int i = 0; i < 2; i++) {
            int id = t + i * 256;           // 0..511
            int r = id >> 5, c4 = id & 31;
            ((float4*)Bs)[id] = ((const float4*)W)[(kc * 16 + r) * 32 + c4];
        }
        __syncthreads();

        #pragma unroll
        for (int k = 0; k < 16; k++) {
            float4 a0 = As4[k * 33 + ty];        // m = ty*4
            float4 a1 = As4[k * 33 + 16 + ty];   // m = 64 + ty*4
            float4 b0 = Bs4[k * 32 + tx];        // n = tx*4
            float4 b1 = Bs4[k * 32 + 16 + tx];   // n = 64 + tx*4
            float a_[8] = {a0.x, a0.y, a0.z, a0.w, a1.x, a1.y, a1.z, a1.w};
            float b_[8] = {b0.x, b0.y, b0.z, b0.w, b1.x, b1.y, b1.z, b1.w};
            #pragma unroll
            for (int rr = 0; rr < 8; rr++)
                #pragma unroll
                for (int cc = 0; cc < 8; cc++)
                    acc[rr][cc] = fmaf(a_[rr], b_[cc], acc[rr][cc]);
        }
    }

    float bv[8] = {0, 0, 0, 0, 0, 0, 0, 0};
    if (bias) {
        float4 q0 = *(const float4*)(bias + tx * 4);
        float4 q1 = *(const float4*)(bias + 64 + tx * 4);
        bv[0]=q0.x; bv[1]=q0.y; bv[2]=q0.z; bv[3]=q0.w;
        bv[4]=q1.x; bv[5]=q1.y; bv[6]=q1.z; bv[7]=q1.w;
    }
    #pragma unroll
    for (int rr = 0; rr < 8; rr++) {
        int m = (rr < 4) ? (ty * 4 + rr) : (64 + ty * 4 + rr - 4);
        int R = row0 + m;
        int orow = (R & (SS - 1)) * SS + (R >> 8);
        float* dst = out + (size_t)orow * CC;
        float vals[8];
        #pragma unroll
        for (int cc = 0; cc < 8; cc++) {
            float v = acc[rr][cc] + bv[cc];
            if (EPI == 1) v = 1.0f / (1.0f + __expf(-v));
            vals[cc] = v;
        }
        *(float4*)(dst + tx * 4)      = make_float4(vals[0], vals[1], vals[2], vals[3]);
        *(float4*)(dst + 64 + tx * 4) = make_float4(vals[4], vals[5], vals[6], vals[7]);
    }
}

// ---------------- attention bias projection: z @ Wb -> bias_t[n][k][i] ---------
__global__ void projb_kernel(const float* __restrict__ z, const float* __restrict__ Wb,
                             float* __restrict__ bias_t) {
    int warp = blockIdx.x * 8 + (threadIdx.x >> 5);
    int lane = threadIdx.x & 31;
    if (warp >= MTOT) return;
    const float4 v = ((const float4*)(z + (size_t)warp * CC))[lane];
    float p0 = 0, p1 = 0, p2 = 0, p3 = 0;
    const float zc[4] = {v.x, v.y, v.z, v.w};
    #pragma unroll
    for (int q = 0; q < 4; q++) {
        int c = lane * 4 + q;
        p0 += zc[q] * Wb[c * 4 + 0];
        p1 += zc[q] * Wb[c * 4 + 1];
        p2 += zc[q] * Wb[c * 4 + 2];
        p3 += zc[q] * Wb[c * 4 + 3];
    }
    #pragma unroll
    for (int off = 16; off; off >>= 1) {
        p0 += __shfl_xor_sync(0xffffffffu, p0, off);
        p1 += __shfl_xor_sync(0xffffffffu, p1, off);
        p2 += __shfl_xor_sync(0xffffffffu, p2, off);
        p3 += __shfl_xor_sync(0xffffffffu, p3, off);
    }
    if (lane == 0) {
        // z row = i*S + j ; value is bias[n][i][k=j] ; store to bias_t[n][j][i]
        int o = (warp & (SS - 1)) * SS + (warp >> 8);
        bias_t[0 * MTOT + o] = p0;
        bias_t[1 * MTOT + o] = p1;
        bias_t[2 * MTOT + o] = p2;
        bias_t[3 * MTOT + o] = p3;
    }
}

// ---------------- attention: one block per (column j, head n) ------------------
// flash-style online softmax, 4 keys per update step (ILP-4 dots, 1 rescale/4).
__global__ void __launch_bounds__(256)
attn_kernel(const float* __restrict__ qt, const float* __restrict__ kt,
            const float* __restrict__ vt, const float* __restrict__ gt,
            const float* __restrict__ bias_t, float* __restrict__ og) {
    const int j = blockIdx.x;
    const int n = blockIdx.y;
    __shared__ float Ks[128 * 32];
    __shared__ float Vs[128 * 32];
    const int t = threadIdx.x;  // == query row i

    float4 qv[8];
    {
        const float4* qp = (const float4*)(qt + (size_t)(j * SS + t) * CC + n * HD);
        #pragma unroll
        for (int i = 0; i < 8; i++) qv[i] = qp[i];
    }
    const float* bcol = bias_t + (size_t)n * MTOT;  // + k*SS + t

    float m = -1e30f, l = 0.f;
    float4 ov[8];
    #pragma unroll
    for (int i = 0; i < 8; i++) ov[i] = make_float4(0.f, 0.f, 0.f, 0.f);

    const float4* Ks4 = (const float4*)Ks;
    const float4* Vs4 = (const float4*)Vs;

    for (int kc = 0; kc < 2; kc++) {
        __syncthreads();
        #pragma unroll
        for (int i = 0; i < 4; i++) {
            int id = t + i * 256;         // float4 id in [0,1024)
            int row = id >> 3, c4 = id & 7;
            size_t src = (size_t)(j * SS + kc * 128 + row) * CC + n * HD + c4 * 4;
            ((float4*)Ks)[id] = *(const float4*)(kt + src);
            ((float4*)Vs)[id] = *(const float4*)(vt + src);
        }
        __syncthreads();

        #pragma unroll 1
        for (int kg = 0; kg < 32; kg++) {
            const int kb = kg * 4;
            // coalesced bias loads (bias_t[n][k][i], consecutive i across warp)
            float b0 = bcol[(kc * 128 + kb + 0) * SS + t];
            float b1 = bcol[(kc * 128 + kb + 1) * SS + t];
            float b2 = bcol[(kc * 128 + kb + 2) * SS + t];
            float b3 = bcol[(kc * 128 + kb + 3) * SS + t];

            float s0 = 0.f, s1 = 0.f, s2 = 0.f, s3 = 0.f;
            #pragma unroll
            for (int d4 = 0; d4 < 8; d4++) {
                float4 q4 = qv[d4];
                float4 k0 = Ks4[(kb + 0) * 8 + d4];
                float4 k1 = Ks4[(kb + 1) * 8 + d4];
                float4 k2 = Ks4[(kb + 2) * 8 + d4];
                float4 k3 = Ks4[(kb + 3) * 8 + d4];
                s0 = fmaf(q4.x, k0.x, s0); s0 = fmaf(q4.y, k0.y, s0);
                s0 = fmaf(q4.z, k0.z, s0); s0 = fmaf(q4.w, k0.w, s0);
                s1 = fmaf(q4.x, k1.x, s1); s1 = fmaf(q4.y, k1.y, s1);
                s1 = fmaf(q4.z, k1.z, s1); s1 = fmaf(q4.w, k1.w, s1);
                s2 = fmaf(q4.x, k2.x, s2); s2 = fmaf(q4.y, k2.y, s2);
                s2 = fmaf(q4.z, k2.z, s2); s2 = fmaf(q4.w, k2.w, s2);
                s3 = fmaf(q4.x, k3.x, s3); s3 = fmaf(q4.y, k3.y, s3);
                s3 = fmaf(q4.z, k3.z, s3); s3 = fmaf(q4.w, k3.w, s3);
            }
            s0 = fmaf(s0, ATT_SCALE, b0);
            s1 = fmaf(s1, ATT_SCALE, b1);
            s2 = fmaf(s2, ATT_SCALE, b2);
            s3 = fmaf(s3, ATT_SCALE, b3);

            float mx = fmaxf(fmaxf(s0, s1), fmaxf(s2, s3));
            float mn = fmaxf(m, mx);
            float al = __expf(m - mn);
            float p0 = __expf(s0 - mn);
            float p1 = __expf(s1 - mn);
            float p2 = __expf(s2 - mn);
            float p3 = __expf(s3 - mn);
            l = fmaf(l, al, (p0 + p1) + (p2 + p3));

            #pragma unroll
            for (int d4 = 0; d4 < 8; d4++) {
                float4 v0 = Vs4[(kb + 0) * 8 + d4];
                float4 v1 = Vs4[(kb + 1) * 8 + d4];
                float4 v2 = Vs4[(kb + 2) * 8 + d4];
                float4 v3 = Vs4[(kb + 3) * 8 + d4];
                float4 o4 = ov[d4];
                o4.x = fmaf(p3, v3.x, fmaf(p2, v2.x, fmaf(p1, v1.x, fmaf(p0, v0.x, o4.x * al))));
                o4.y = fmaf(p3, v3.y, fmaf(p2, v2.y, fmaf(p1, v1.y, fmaf(p0, v0.y, o4.y * al))));
                o4.z = fmaf(p3, v3.z, fmaf(p2, v2.z, fmaf(p1, v1.z, fmaf(p0, v0.z, o4.z * al))));
                o4.w = fmaf(p3, v3.w, fmaf(p2, v2.w, fmaf(p1, v1.w, fmaf(p0, v0.w, o4.w * al))));
                ov[d4] = o4;
            }
            m = mn;
        }
    }

    float inv = 1.f / l;
    const float4* gp = (const float4*)(gt + (size_t)(j * SS + t) * CC + n * HD);
    float4* op = (float4*)(og + (size_t)(j * SS + t) * CC + n * HD);
    #pragma unroll
    for (int i = 0; i < 8; i++) {
        float4 g4 = gp[i];
        float4 r;
        r.x = ov[i].x * inv * g4.x;
        r.y = ov[i].y * inv * g4.y;
        r.z = ov[i].z * inv * g4.z;
        r.w = ov[i].w * inv * g4.w;
        op[i] = r;
    }
}

// ---------------- launch -------------------------------------------------------
extern "C" void kernel_launch(void* const* d_in, const int* in_sizes, int n_in,
                              void* d_out, int out_size) {
    const float* pair  = (const float*)d_in[0];
    const float* gamma = (const float*)d_in[1];
    const float* beta  = (const float*)d_in[2];
    const float* Wq    = (const float*)d_in[3];
    const float* Wk    = (const float*)d_in[4];
    const float* Wv    = (const float*)d_in[5];
    const float* Wb    = (const float*)d_in[6];
    const float* Wg    = (const float*)d_in[7];
    const float* bg    = (const float*)d_in[8];
    const float* Wo    = (const float*)d_in[9];
    const float* bo    = (const float*)d_in[10];
    float* out = (float*)d_out;

    float* base = nullptr;
    cudaGetSymbolAddress((void**)&base, g_scratch);
    float* z    = base;
    float* qt   = base + 1 * 8388608;
    float* kt   = base + 2 * 8388608;
    float* vt   = base + 3 * 8388608;
    float* gt   = base + 4 * 8388608;
    float* og   = base + 5 * 8388608;
    float* bias = base + 6 * 8388608;

    ln_kernel<<<MTOT / 8, 256>>>(pair, gamma, beta, z);

    gemm128_kernel<0><<<MTOT / 128, 256>>>(z, Wq, nullptr, qt);
    gemm128_kernel<0><<<MTOT / 128, 256>>>(z, Wk, nullptr, kt);
    gemm128_kernel<0><<<MTOT / 128, 256>>>(z, Wv, nullptr, vt);
    gemm128_kernel<1><<<MTOT / 128, 256>>>(z, Wg, bg, gt);
    projb_kernel<<<MTOT / 8, 256>>>(z, Wb, bias);

    attn_kernel<<<dim3(SS, NH), 256>>>(qt, kt, vt, gt, bias, og);

    gemm128_kernel<0><<<MTOT / 128, 256>>>(og, Wo, bo, out);
}

// round 5
// speedup vs baseline: 2.7952x; 1.2574x over previous
#include <cuda_runtime.h>
#include <cuda_bf16.h>
#include <math.h>
#include <stdint.h>

#define SS 256       // sequence
#define CC 128       // channels
#define NH 4
#define HD 32
#define MTOT (SS*SS) // 65536
#define ATT_SCALE 0.17677669529663687f  // 1/sqrt(32)
#define LN_EPS 1e-5f

// ---------------- scratch (no allocation allowed; single big __device__ blob) ---
// layout (floats):
//   z   : [0,            8388608)
//   qt  : [8388608,     16777216)   transposed: row = j*S + i
//   kt  : [16777216,    25165824)
//   vt  : [25165824,    33554432)
//   gt  : [33554432,    41943040)
//   og  : [41943040,    50331648)   gated attention output, row = j*S + i
//   bias_t: [50331648, +4*65536)    [n][k][i]   (transposed for coalesced reads)
__device__ float g_scratch[50331648 + NH*MTOT];

__device__ __forceinline__ uint32_t f2tf32(float f) {
    uint32_t r;
    asm("cvt.rna.tf32.f32 %0, %1;" : "=r"(r) : "f"(f));
    return r;
}

__device__ __forceinline__ void mma_tf32(float4& c, uint32_t a0, uint32_t a1,
                                         uint32_t a2, uint32_t a3,
                                         uint32_t b0, uint32_t b1) {
    asm volatile(
        "mma.sync.aligned.m16n8k8.row.col.f32.tf32.tf32.f32 "
        "{%0,%1,%2,%3}, {%4,%5,%6,%7}, {%8,%9}, {%0,%1,%2,%3};"
        : "+f"(c.x), "+f"(c.y), "+f"(c.z), "+f"(c.w)
        : "r"(a0), "r"(a1), "r"(a2), "r"(a3), "r"(b0), "r"(b1));
}

// ---------------- LayerNorm: one warp per row of 128 channels -------------------
__global__ void ln_kernel(const float* __restrict__ x, const float* __restrict__ gamma,
                          const float* __restrict__ beta, float* __restrict__ z) {
    int warp = blockIdx.x * 8 + (threadIdx.x >> 5);
    int lane = threadIdx.x & 31;
    if (warp >= MTOT) return;
    const float4 v = ((const float4*)(x + (size_t)warp * CC))[lane];
    float s  = v.x + v.y + v.z + v.w;
    float sq = v.x*v.x + v.y*v.y + v.z*v.z + v.w*v.w;
    #pragma unroll
    for (int off = 16; off; off >>= 1) {
        s  += __shfl_xor_sync(0xffffffffu, s,  off);
        sq += __shfl_xor_sync(0xffffffffu, sq, off);
    }
    float mu  = s * (1.0f / CC);
    float var = sq * (1.0f / CC) - mu * mu;
    float rs  = rsqrtf(var + LN_EPS);
    const float4 g4 = ((const float4*)gamma)[lane];
    const float4 b4 = ((const float4*)beta)[lane];
    float4 o;
    o.x = (v.x - mu) * rs * g4.x + b4.x;
    o.y = (v.y - mu) * rs * g4.y + b4.y;
    o.z = (v.z - mu) * rs * g4.z + b4.z;
    o.w = (v.w - mu) * rs * g4.w + b4.w;
    ((float4*)(z + (size_t)warp * CC))[lane] = o;
}

// ---------------- tf32 MMA GEMM: [65536,128] x (up to 4x) [128,128] ------------
// One block = 128 rows. Full-K A tile staged once in smem (tf32, crosswise
// layout: element (r, k) at As[(k>>5)*4608 + r*36 + (k&3)*8 + ((k&31)>>2)]),
// then loop over nw weight matrices; B staged per 32-k chunk row-major.
// Writes with transposed spatial index: input row R -> (R & 255)*256 + (R >> 8).
// Row stride in As is 36 floats = 9 float4.  All fragment offsets below are in
// float4 units: +8 rows = +72 f4, +16 rows = +144 f4.
struct GemmArgs {
    const float* A;
    const float* W[4];
    float*       out[4];
    const float* bias[4];  // nullptr if none
    int          sig[4];   // 1 => sigmoid epilogue
    int          nw;
};

__global__ void __launch_bounds__(256, 2)
mma_gemm_kernel(GemmArgs ga) {
    extern __shared__ float sm[];
    float* As = sm;                  // 4 * 128 * 36 = 18432 floats
    float* Bs = sm + 18432;          // 32 * 132 = 4224 floats
    const int t = threadIdx.x;
    const int lane = t & 31, warp = t >> 5;
    const int wm = warp & 3, wn = warp >> 2;    // warp grid 4 (M) x 2 (N)
    const int m0w = wm * 32, n0w = wn * 64;
    const int g = lane >> 2, q = lane & 3;
    const int row0 = blockIdx.x * 128;

    // ---- stage A (full K=128), converted to tf32, crosswise layout ----
    #pragma unroll
    for (int i = 0; i < 16; i++) {
        int id = t + i * 256;                 // 0..4095 float4s
        int r = id >> 5, c4g = id & 31;       // row, k-float4 (0..31)
        float4 v = ((const float4*)ga.A)[(size_t)(row0 + r) * 32 + c4g];
        int kc = c4g >> 3, c4 = c4g & 7;
        float* dst = As + kc * 4608 + r * 36 + c4;
        dst[0]  = __uint_as_float(f2tf32(v.x));
        dst[8]  = __uint_as_float(f2tf32(v.y));
        dst[16] = __uint_as_float(f2tf32(v.z));
        dst[24] = __uint_as_float(f2tf32(v.w));
    }

    const float4* As4 = (const float4*)As;
    const int abase0 = (m0w + g) * 9 + 2 * q;   // float4 units

    for (int w = 0; w < ga.nw; w++) {
        float4 acc[2][8];
        #pragma unroll
        for (int mt = 0; mt < 2; mt++)
            #pragma unroll
            for (int nt = 0; nt < 8; nt++) acc[mt][nt] = make_float4(0.f, 0.f, 0.f, 0.f);

        const float* W = ga.W[w];
        for (int kc = 0; kc < 4; kc++) {
            __syncthreads();   // previous chunk's mma reads of Bs complete
            // ---- stage B chunk: k in [kc*32, kc*32+32), all 128 n (tf32) ----
            #pragma unroll
            for (int i = 0; i < 4; i++) {
                int id = t + i * 256;          // 0..1023 float4s
                int kk = id >> 5, n4 = id & 31;
                float4 v = ((const float4*)W)[(size_t)(kc * 32 + kk) * 32 + n4];
                float4 o;
                o.x = __uint_as_float(f2tf32(v.x));
                o.y = __uint_as_float(f2tf32(v.y));
                o.z = __uint_as_float(f2tf32(v.z));
                o.w = __uint_as_float(f2tf32(v.w));
                ((float4*)Bs)[kk * 33 + n4] = o;   // Bs[k][n], row pad 132
            }
            __syncthreads();

            const int abase = kc * 1152 + abase0;
            #pragma unroll
            for (int tp = 0; tp < 2; tp++) {       // k-step pairs
                float4 alo[2], ahi[2];
                #pragma unroll
                for (int mt = 0; mt < 2; mt++) {
                    alo[mt] = As4[abase + mt * 144 + tp];        // rows m0w+g + 16*mt
                    ahi[mt] = As4[abase + mt * 144 + 72 + tp];   // +8 rows (8*9=72 f4)
                }
                #pragma unroll
                for (int th = 0; th < 2; th++) {   // step within pair
                    const int krow = (tp * 2 + th) * 8 + q;
                    uint32_t a0[2], a1[2], a2[2], a3[2];
                    #pragma unroll
                    for (int mt = 0; mt < 2; mt++) {
                        a0[mt] = __float_as_uint(th ? alo[mt].z : alo[mt].x);
                        a2[mt] = __float_as_uint(th ? alo[mt].w : alo[mt].y);
                        a1[mt] = __float_as_uint(th ? ahi[mt].z : ahi[mt].x);
                        a3[mt] = __float_as_uint(th ? ahi[mt].w : ahi[mt].y);
                    }
                    #pragma unroll
                    for (int nt = 0; nt < 8; nt++) {
                        const int cn = n0w + nt * 8 + g;
                        uint32_t b0 = __float_as_uint(Bs[krow * 132 + cn]);
                        uint32_t b1 = __float_as_uint(Bs[(krow + 4) * 132 + cn]);
                        mma_tf32(acc[0][nt], a0[0], a1[0], a2[0], a3[0], b0, b1);
                        mma_tf32(acc[1][nt], a0[1], a1[1], a2[1], a3[1], b0, b1);
                    }
                }
            }
        }

        // ---- epilogue for this weight matrix ----
        const float* bias = ga.bias[w];
        const int sig = ga.sig[w];
        float* out = ga.out[w];
        float2 bv[8];
        #pragma unroll
        for (int nt = 0; nt < 8; nt++) {
            if (bias) bv[nt] = *(const float2*)(bias + n0w + nt * 8 + 2 * q);
            else      bv[nt] = make_float2(0.f, 0.f);
        }
        #pragma unroll
        for (int mt = 0; mt < 2; mt++) {
            int r  = row0 + m0w + mt * 16 + g;
            int r2 = r + 8;
            int or0 = ((r  & 255) << 8) | (r  >> 8);
            int or1 = ((r2 & 255) << 8) | (r2 >> 8);
            #pragma unroll
            for (int nt = 0; nt < 8; nt++) {
                int col = n0w + nt * 8 + 2 * q;
                float4 c = acc[mt][nt];
                float v0 = c.x + bv[nt].x, v1 = c.y + bv[nt].y;
                float v2 = c.z + bv[nt].x, v3 = c.w + bv[nt].y;
                if (sig) {
                    v0 = 1.0f / (1.0f + __expf(-v0));
                    v1 = 1.0f / (1.0f + __expf(-v1));
                    v2 = 1.0f / (1.0f + __expf(-v2));
                    v3 = 1.0f / (1.0f + __expf(-v3));
                }
                *(float2*)(out + (size_t)or0 * CC + col) = make_float2(v0, v1);
                *(float2*)(out + (size_t)or1 * CC + col) = make_float2(v2, v3);
            }
        }
    }
}

// ---------------- attention bias projection: z @ Wb -> bias_t[n][k][i] ---------
__global__ void projb_kernel(const float* __restrict__ z, const float* __restrict__ Wb,
                             float* __restrict__ bias_t) {
    int warp = blockIdx.x * 8 + (threadIdx.x >> 5);
    int lane = threadIdx.x & 31;
    if (warp >= MTOT) return;
    const float4 v = ((const float4*)(z + (size_t)warp * CC))[lane];
    float p0 = 0, p1 = 0, p2 = 0, p3 = 0;
    const float zc[4] = {v.x, v.y, v.z, v.w};
    #pragma unroll
    for (int qq = 0; qq < 4; qq++) {
        int c = lane * 4 + qq;
        p0 += zc[qq] * Wb[c * 4 + 0];
        p1 += zc[qq] * Wb[c * 4 + 1];
        p2 += zc[qq] * Wb[c * 4 + 2];
        p3 += zc[qq] * Wb[c * 4 + 3];
    }
    #pragma unroll
    for (int off = 16; off; off >>= 1) {
        p0 += __shfl_xor_sync(0xffffffffu, p0, off);
        p1 += __shfl_xor_sync(0xffffffffu, p1, off);
        p2 += __shfl_xor_sync(0xffffffffu, p2, off);
        p3 += __shfl_xor_sync(0xffffffffu, p3, off);
    }
    if (lane == 0) {
        // z row = i*S + j ; value is bias[n][i][k=j] ; store to bias_t[n][j][i]
        int o = (warp & (SS - 1)) * SS + (warp >> 8);
        bias_t[0 * MTOT + o] = p0;
        bias_t[1 * MTOT + o] = p1;
        bias_t[2 * MTOT + o] = p2;
        bias_t[3 * MTOT + o] = p3;
    }
}

// ---------------- attention: one block per (column j, head n) ------------------
// flash-style online softmax, 4 keys per update step (ILP-4 dots, 1 rescale/4).
__global__ void __launch_bounds__(256)
attn_kernel(const float* __restrict__ qt, const float* __restrict__ kt,
            const float* __restrict__ vt, const float* __restrict__ gt,
            const float* __restrict__ bias_t, float* __restrict__ og) {
    const int j = blockIdx.x;
    const int n = blockIdx.y;
    __shared__ float Ks[128 * 32];
    __shared__ float Vs[128 * 32];
    const int t = threadIdx.x;  // == query row i

    float4 qv[8];
    {
        const float4* qp = (const float4*)(qt + (size_t)(j * SS + t) * CC + n * HD);
        #pragma unroll
        for (int i = 0; i < 8; i++) qv[i] = qp[i];
    }
    const float* bcol = bias_t + (size_t)n * MTOT;  // + k*SS + t

    float m = -1e30f, l = 0.f;
    float4 ov[8];
    #pragma unroll
    for (int i = 0; i < 8; i++) ov[i] = make_float4(0.f, 0.f, 0.f, 0.f);

    const float4* Ks4 = (const float4*)Ks;
    const float4* Vs4 = (const float4*)Vs;

    for (int kc = 0; kc < 2; kc++) {
        __syncthreads();
        #pragma unroll
        for (int i = 0; i < 4; i++) {
            int id = t + i * 256;         // float4 id in [0,1024)
            int row = id >> 3, c4 = id & 7;
            size_t src = (size_t)(j * SS + kc * 128 + row) * CC + n * HD + c4 * 4;
            ((float4*)Ks)[id] = *(const float4*)(kt + src);
            ((float4*)Vs)[id] = *(const float4*)(vt + src);
        }
        __syncthreads();

        #pragma unroll 1
        for (int kg = 0; kg < 32; kg++) {
            const int kb = kg * 4;
            float b0 = bcol[(kc * 128 + kb + 0) * SS + t];
            float b1 = bcol[(kc * 128 + kb + 1) * SS + t];
            float b2 = bcol[(kc * 128 + kb + 2) * SS + t];
            float b3 = bcol[(kc * 128 + kb + 3) * SS + t];

            float s0 = 0.f, s1 = 0.f, s2 = 0.f, s3 = 0.f;
            #pragma unroll
            for (int d4 = 0; d4 < 8; d4++) {
                float4 q4 = qv[d4];
                float4 k0 = Ks4[(kb + 0) * 8 + d4];
                float4 k1 = Ks4[(kb + 1) * 8 + d4];
                float4 k2 = Ks4[(kb + 2) * 8 + d4];
                float4 k3 = Ks4[(kb + 3) * 8 + d4];
                s0 = fmaf(q4.x, k0.x, s0); s0 = fmaf(q4.y, k0.y, s0);
                s0 = fmaf(q4.z, k0.z, s0); s0 = fmaf(q4.w, k0.w, s0);
                s1 = fmaf(q4.x, k1.x, s1); s1 = fmaf(q4.y, k1.y, s1);
                s1 = fmaf(q4.z, k1.z, s1); s1 = fmaf(q4.w, k1.w, s1);
                s2 = fmaf(q4.x, k2.x, s2); s2 = fmaf(q4.y, k2.y, s2);
                s2 = fmaf(q4.z, k2.z, s2); s2 = fmaf(q4.w, k2.w, s2);
                s3 = fmaf(q4.x, k3.x, s3); s3 = fmaf(q4.y, k3.y, s3);
                s3 = fmaf(q4.z, k3.z, s3); s3 = fmaf(q4.w, k3.w, s3);
            }
            s0 = fmaf(s0, ATT_SCALE, b0);
            s1 = fmaf(s1, ATT_SCALE, b1);
            s2 = fmaf(s2, ATT_SCALE, b2);
            s3 = fmaf(s3, ATT_SCALE, b3);

            float mx = fmaxf(fmaxf(s0, s1), fmaxf(s2, s3));
            float mn = fmaxf(m, mx);
            float al = __expf(m - mn);
            float p0 = __expf(s0 - mn);
            float p1 = __expf(s1 - mn);
            float p2 = __expf(s2 - mn);
            float p3 = __expf(s3 - mn);
            l = fmaf(l, al, (p0 + p1) + (p2 + p3));

            #pragma unroll
            for (int d4 = 0; d4 < 8; d4++) {
                float4 v0 = Vs4[(kb + 0) * 8 + d4];
                float4 v1 = Vs4[(kb + 1) * 8 + d4];
                float4 v2 = Vs4[(kb + 2) * 8 + d4];
                float4 v3 = Vs4[(kb + 3) * 8 + d4];
                float4 o4 = ov[d4];
                o4.x = fmaf(p3, v3.x, fmaf(p2, v2.x, fmaf(p1, v1.x, fmaf(p0, v0.x, o4.x * al))));
                o4.y = fmaf(p3, v3.y, fmaf(p2, v2.y, fmaf(p1, v1.y, fmaf(p0, v0.y, o4.y * al))));
                o4.z = fmaf(p3, v3.z, fmaf(p2, v2.z, fmaf(p1, v1.z, fmaf(p0, v0.z, o4.z * al))));
                o4.w = fmaf(p3, v3.w, fmaf(p2, v2.w, fmaf(p1, v1.w, fmaf(p0, v0.w, o4.w * al))));
                ov[d4] = o4;
            }
            m = mn;
        }
    }

    float inv = 1.f / l;
    const float4* gp = (const float4*)(gt + (size_t)(j * SS + t) * CC + n * HD);
    float4* op = (float4*)(og + (size_t)(j * SS + t) * CC + n * HD);
    #pragma unroll
    for (int i = 0; i < 8; i++) {
        float4 g4 = gp[i];
        float4 r;
        r.x = ov[i].x * inv * g4.x;
        r.y = ov[i].y * inv * g4.y;
        r.z = ov[i].z * inv * g4.z;
        r.w = ov[i].w * inv * g4.w;
        op[i] = r;
    }
}

// ---------------- launch -------------------------------------------------------
extern "C" void kernel_launch(void* const* d_in, const int* in_sizes, int n_in,
                              void* d_out, int out_size) {
    const float* pair  = (const float*)d_in[0];
    const float* gamma = (const float*)d_in[1];
    const float* beta  = (const float*)d_in[2];
    const float* Wq    = (const float*)d_in[3];
    const float* Wk    = (const float*)d_in[4];
    const float* Wv    = (const float*)d_in[5];
    const float* Wb    = (const float*)d_in[6];
    const float* Wg    = (const float*)d_in[7];
    const float* bg    = (const float*)d_in[8];
    const float* Wo    = (const float*)d_in[9];
    const float* bo    = (const float*)d_in[10];
    float* out = (float*)d_out;

    float* base = nullptr;
    cudaGetSymbolAddress((void**)&base, g_scratch);
    float* z    = base;
    float* qt   = base + 1 * 8388608;
    float* kt   = base + 2 * 8388608;
    float* vt   = base + 3 * 8388608;
    float* gt   = base + 4 * 8388608;
    float* og   = base + 5 * 8388608;
    float* bias = base + 6 * 8388608;

    const int GEMM_SMEM = (18432 + 4224) * 4;   // 90624 bytes
    cudaFuncSetAttribute(mma_gemm_kernel,
                         cudaFuncAttributeMaxDynamicSharedMemorySize, GEMM_SMEM);

    ln_kernel<<<MTOT / 8, 256>>>(pair, gamma, beta, z);

    GemmArgs pa;
    pa.A = z;
    pa.W[0] = Wq; pa.W[1] = Wk; pa.W[2] = Wv; pa.W[3] = Wg;
    pa.out[0] = qt; pa.out[1] = kt; pa.out[2] = vt; pa.out[3] = gt;
    pa.bias[0] = nullptr; pa.bias[1] = nullptr; pa.bias[2] = nullptr; pa.bias[3] = bg;
    pa.sig[0] = 0; pa.sig[1] = 0; pa.sig[2] = 0; pa.sig[3] = 1;
    pa.nw = 4;
    mma_gemm_kernel<<<MTOT / 128, 256, GEMM_SMEM>>>(pa);

    projb_kernel<<<MTOT / 8, 256>>>(z, Wb, bias);

    attn_kernel<<<dim3(SS, NH), 256>>>(qt, kt, vt, gt, bias, og);

    GemmArgs oa;
    oa.A = og;
    oa.W[0] = Wo;
    oa.out[0] = out;
    oa.bias[0] = bo;
    oa.sig[0] = 0;
    oa.nw = 1;
    mma_gemm_kernel<<<MTOT / 128, 256, GEMM_SMEM>>>(oa);
}

// round 6
// speedup vs baseline: 4.0413x; 1.4458x over previous
#include <cuda_runtime.h>
#include <cuda_bf16.h>
#include <math.h>
#include <stdint.h>

#define SS 256       // sequence
#define CC 128       // channels
#define NH 4
#define HD 32
#define MTOT (SS*SS) // 65536
#define ATT_SCALE 0.17677669529663687f  // 1/sqrt(32)
#define LOG2E 1.4426950408889634f
#define LN_EPS 1e-5f

// ---------------- scratch (no allocation allowed; single big __device__ blob) ---
// layout (floats):
//   z   : [0,            8388608)
//   qt  : [8388608,     16777216)   transposed: row = j*S + i
//   kt  : [16777216,    25165824)
//   vt  : [25165824,    33554432)
//   gt  : [33554432,    41943040)
//   og  : [41943040,    50331648)   gated attention output, row = j*S + i
//   bias_t: [50331648, +4*65536)    [n][k][i]
__device__ float g_scratch[50331648 + NH*MTOT];

__device__ __forceinline__ uint32_t f2tf32(float f) {
    uint32_t r;
    asm("cvt.rna.tf32.f32 %0, %1;" : "=r"(r) : "f"(f));
    return r;
}
__device__ __forceinline__ float tf32f(float f) { return __uint_as_float(f2tf32(f)); }

__device__ __forceinline__ float fexp2(float x) {
    float r;
    asm("ex2.approx.ftz.f32 %0, %1;" : "=f"(r) : "f"(x));
    return r;
}

__device__ __forceinline__ void mma_tf32(float4& c, uint32_t a0, uint32_t a1,
                                         uint32_t a2, uint32_t a3,
                                         uint32_t b0, uint32_t b1) {
    asm volatile(
        "mma.sync.aligned.m16n8k8.row.col.f32.tf32.tf32.f32 "
        "{%0,%1,%2,%3}, {%4,%5,%6,%7}, {%8,%9}, {%0,%1,%2,%3};"
        : "+f"(c.x), "+f"(c.y), "+f"(c.z), "+f"(c.w)
        : "r"(a0), "r"(a1), "r"(a2), "r"(a3), "r"(b0), "r"(b1));
}

// ---------------- LayerNorm: one warp per row of 128 channels -------------------
__global__ void ln_kernel(const float* __restrict__ x, const float* __restrict__ gamma,
                          const float* __restrict__ beta, float* __restrict__ z) {
    int warp = blockIdx.x * 8 + (threadIdx.x >> 5);
    int lane = threadIdx.x & 31;
    if (warp >= MTOT) return;
    const float4 v = ((const float4*)(x + (size_t)warp * CC))[lane];
    float s  = v.x + v.y + v.z + v.w;
    float sq = v.x*v.x + v.y*v.y + v.z*v.z + v.w*v.w;
    #pragma unroll
    for (int off = 16; off; off >>= 1) {
        s  += __shfl_xor_sync(0xffffffffu, s,  off);
        sq += __shfl_xor_sync(0xffffffffu, sq, off);
    }
    float mu  = s * (1.0f / CC);
    float var = sq * (1.0f / CC) - mu * mu;
    float rs  = rsqrtf(var + LN_EPS);
    const float4 g4 = ((const float4*)gamma)[lane];
    const float4 b4 = ((const float4*)beta)[lane];
    float4 o;
    o.x = (v.x - mu) * rs * g4.x + b4.x;
    o.y = (v.y - mu) * rs * g4.y + b4.y;
    o.z = (v.z - mu) * rs * g4.z + b4.z;
    o.w = (v.w - mu) * rs * g4.w + b4.w;
    ((float4*)(z + (size_t)warp * CC))[lane] = o;
}

// ---------------- tf32 MMA GEMM: [65536,128] x (up to 4x) [128,128] ------------
struct GemmArgs {
    const float* A;
    const float* W[4];
    float*       out[4];
    const float* bias[4];
    int          sig[4];
    int          nw;
};

__global__ void __launch_bounds__(256, 2)
mma_gemm_kernel(GemmArgs ga) {
    extern __shared__ float sm[];
    float* As = sm;                  // 4 * 128 * 36 = 18432 floats
    float* Bs = sm + 18432;          // 32 * 132 = 4224 floats
    const int t = threadIdx.x;
    const int lane = t & 31, warp = t >> 5;
    const int wm = warp & 3, wn = warp >> 2;
    const int m0w = wm * 32, n0w = wn * 64;
    const int g = lane >> 2, q = lane & 3;
    const int row0 = blockIdx.x * 128;

    #pragma unroll
    for (int i = 0; i < 16; i++) {
        int id = t + i * 256;
        int r = id >> 5, c4g = id & 31;
        float4 v = ((const float4*)ga.A)[(size_t)(row0 + r) * 32 + c4g];
        int kc = c4g >> 3, c4 = c4g & 7;
        float* dst = As + kc * 4608 + r * 36 + c4;
        dst[0]  = tf32f(v.x);
        dst[8]  = tf32f(v.y);
        dst[16] = tf32f(v.z);
        dst[24] = tf32f(v.w);
    }

    const float4* As4 = (const float4*)As;
    const int abase0 = (m0w + g) * 9 + 2 * q;   // float4 units

    for (int w = 0; w < ga.nw; w++) {
        float4 acc[2][8];
        #pragma unroll
        for (int mt = 0; mt < 2; mt++)
            #pragma unroll
            for (int nt = 0; nt < 8; nt++) acc[mt][nt] = make_float4(0.f, 0.f, 0.f, 0.f);

        const float* W = ga.W[w];
        for (int kc = 0; kc < 4; kc++) {
            __syncthreads();
            #pragma unroll
            for (int i = 0; i < 4; i++) {
                int id = t + i * 256;
                int kk = id >> 5, n4 = id & 31;
                float4 v = ((const float4*)W)[(size_t)(kc * 32 + kk) * 32 + n4];
                float4 o;
                o.x = tf32f(v.x); o.y = tf32f(v.y); o.z = tf32f(v.z); o.w = tf32f(v.w);
                ((float4*)Bs)[kk * 33 + n4] = o;
            }
            __syncthreads();

            const int abase = kc * 1152 + abase0;
            #pragma unroll
            for (int tp = 0; tp < 2; tp++) {
                float4 alo[2], ahi[2];
                #pragma unroll
                for (int mt = 0; mt < 2; mt++) {
                    alo[mt] = As4[abase + mt * 144 + tp];
                    ahi[mt] = As4[abase + mt * 144 + 72 + tp];
                }
                #pragma unroll
                for (int th = 0; th < 2; th++) {
                    const int krow = (tp * 2 + th) * 8 + q;
                    uint32_t a0[2], a1[2], a2[2], a3[2];
                    #pragma unroll
                    for (int mt = 0; mt < 2; mt++) {
                        a0[mt] = __float_as_uint(th ? alo[mt].z : alo[mt].x);
                        a2[mt] = __float_as_uint(th ? alo[mt].w : alo[mt].y);
                        a1[mt] = __float_as_uint(th ? ahi[mt].z : ahi[mt].x);
                        a3[mt] = __float_as_uint(th ? ahi[mt].w : ahi[mt].y);
                    }
                    #pragma unroll
                    for (int nt = 0; nt < 8; nt++) {
                        const int cn = n0w + nt * 8 + g;
                        uint32_t b0 = __float_as_uint(Bs[krow * 132 + cn]);
                        uint32_t b1 = __float_as_uint(Bs[(krow + 4) * 132 + cn]);
                        mma_tf32(acc[0][nt], a0[0], a1[0], a2[0], a3[0], b0, b1);
                        mma_tf32(acc[1][nt], a0[1], a1[1], a2[1], a3[1], b0, b1);
                    }
                }
            }
        }

        const float* bias = ga.bias[w];
        const int sig = ga.sig[w];
        float* out = ga.out[w];
        float2 bv[8];
        #pragma unroll
        for (int nt = 0; nt < 8; nt++) {
            if (bias) bv[nt] = *(const float2*)(bias + n0w + nt * 8 + 2 * q);
            else      bv[nt] = make_float2(0.f, 0.f);
        }
        #pragma unroll
        for (int mt = 0; mt < 2; mt++) {
            int r  = row0 + m0w + mt * 16 + g;
            int r2 = r + 8;
            int or0 = ((r  & 255) << 8) | (r  >> 8);
            int or1 = ((r2 & 255) << 8) | (r2 >> 8);
            #pragma unroll
            for (int nt = 0; nt < 8; nt++) {
                int col = n0w + nt * 8 + 2 * q;
                float4 c = acc[mt][nt];
                float v0 = c.x + bv[nt].x, v1 = c.y + bv[nt].y;
                float v2 = c.z + bv[nt].x, v3 = c.w + bv[nt].y;
                if (sig) {
                    v0 = 1.0f / (1.0f + __expf(-v0));
                    v1 = 1.0f / (1.0f + __expf(-v1));
                    v2 = 1.0f / (1.0f + __expf(-v2));
                    v3 = 1.0f / (1.0f + __expf(-v3));
                }
                *(float2*)(out + (size_t)or0 * CC + col) = make_float2(v0, v1);
                *(float2*)(out + (size_t)or1 * CC + col) = make_float2(v2, v3);
            }
        }
    }
}

// ---------------- attention bias projection: z @ Wb -> bias_t[n][k][i] ---------
__global__ void projb_kernel(const float* __restrict__ z, const float* __restrict__ Wb,
                             float* __restrict__ bias_t) {
    int warp = blockIdx.x * 8 + (threadIdx.x >> 5);
    int lane = threadIdx.x & 31;
    if (warp >= MTOT) return;
    const float4 v = ((const float4*)(z + (size_t)warp * CC))[lane];
    float p0 = 0, p1 = 0, p2 = 0, p3 = 0;
    const float zc[4] = {v.x, v.y, v.z, v.w};
    #pragma unroll
    for (int qq = 0; qq < 4; qq++) {
        int c = lane * 4 + qq;
        p0 += zc[qq] * Wb[c * 4 + 0];
        p1 += zc[qq] * Wb[c * 4 + 1];
        p2 += zc[qq] * Wb[c * 4 + 2];
        p3 += zc[qq] * Wb[c * 4 + 3];
    }
    #pragma unroll
    for (int off = 16; off; off >>= 1) {
        p0 += __shfl_xor_sync(0xffffffffu, p0, off);
        p1 += __shfl_xor_sync(0xffffffffu, p1, off);
        p2 += __shfl_xor_sync(0xffffffffu, p2, off);
        p3 += __shfl_xor_sync(0xffffffffu, p3, off);
    }
    if (lane == 0) {
        int o = (warp & (SS - 1)) * SS + (warp >> 8);
        bias_t[0 * MTOT + o] = p0;
        bias_t[1 * MTOT + o] = p1;
        bias_t[2 * MTOT + o] = p2;
        bias_t[3 * MTOT + o] = p3;
    }
}

// ---------------- tf32 MMA flash attention: one block per (j, head n) ----------
// 8 warps; warp w owns query rows [32w, 32w+32). Keys processed in 4 chunks of
// 64. K staged [d][key] stride 73 (conflict-free STS / ~1.1x LDS); V staged
// [key][d] stride 41 (conflict-free STS / ~1.1x LDS). Softmax in log2 domain.
__global__ void __launch_bounds__(256, 1)
attn_mma_kernel(const float* __restrict__ qt, const float* __restrict__ kt,
                const float* __restrict__ vt, const float* __restrict__ gt,
                const float* __restrict__ bias_t, float* __restrict__ og) {
    __shared__ float Ks[32 * 73];
    __shared__ float Vs[64 * 41];
    const int j = blockIdx.x, n = blockIdx.y;
    const int t = threadIdx.x;
    const int lane = t & 31, w = t >> 5;
    const int g = lane >> 2, q = lane & 3;
    const int I0 = w * 32;
    const float SCALE2 = ATT_SCALE * LOG2E;

    // ---- Q fragments (tf32), rows I0+16mt+g (+8), cols 8kt+q (+4) ----
    uint32_t qa[2][4][4];
    #pragma unroll
    for (int mt = 0; mt < 2; mt++) {
        const float* qp0 = qt + (size_t)(j * SS + I0 + mt * 16 + g) * CC + n * HD;
        const float* qp1 = qp0 + 8 * CC;
        #pragma unroll
        for (int kt = 0; kt < 4; kt++) {
            qa[mt][kt][0] = f2tf32(qp0[kt * 8 + q]);
            qa[mt][kt][1] = f2tf32(qp1[kt * 8 + q]);
            qa[mt][kt][2] = f2tf32(qp0[kt * 8 + q + 4]);
            qa[mt][kt][3] = f2tf32(qp1[kt * 8 + q + 4]);
        }
    }

    float m_[2][2], l_[2][2];
    float4 o_[2][4];
    #pragma unroll
    for (int mt = 0; mt < 2; mt++) {
        m_[mt][0] = m_[mt][1] = -1e30f;
        l_[mt][0] = l_[mt][1] = 0.f;
        #pragma unroll
        for (int nt = 0; nt < 4; nt++) o_[mt][nt] = make_float4(0.f, 0.f, 0.f, 0.f);
    }

    const float* bn = bias_t + (size_t)n * MTOT;
    const int src0 = (lane & ~3) | (q >> 1);
    const int src2 = src0 + 2;

    for (int c = 0; c < 4; c++) {
        __syncthreads();
        // ---- stage K/V chunk (64 keys), tf32 ----
        #pragma unroll
        for (int i = 0; i < 2; i++) {
            int id = t + i * 256;             // 0..511
            int key = id >> 3, c4 = id & 7;
            size_t src = (size_t)(j * SS + c * 64 + key) * CC + n * HD + c4 * 4;
            float4 kv = *(const float4*)(kt + src);
            float4 vv = *(const float4*)(vt + src);
            Ks[(c4 * 4 + 0) * 73 + key] = tf32f(kv.x);
            Ks[(c4 * 4 + 1) * 73 + key] = tf32f(kv.y);
            Ks[(c4 * 4 + 2) * 73 + key] = tf32f(kv.z);
            Ks[(c4 * 4 + 3) * 73 + key] = tf32f(kv.w);
            float* vd = Vs + key * 41 + c4 * 4;
            vd[0] = tf32f(vv.x); vd[1] = tf32f(vv.y);
            vd[2] = tf32f(vv.z); vd[3] = tf32f(vv.w);
        }
        __syncthreads();

        // ---- S = Q K^T ----
        float4 sc[2][8];
        #pragma unroll
        for (int mt = 0; mt < 2; mt++)
            #pragma unroll
            for (int nt = 0; nt < 8; nt++) sc[mt][nt] = make_float4(0.f, 0.f, 0.f, 0.f);
        #pragma unroll
        for (int nt = 0; nt < 8; nt++) {
            #pragma unroll
            for (int kt = 0; kt < 4; kt++) {
                uint32_t b0 = __float_as_uint(Ks[(kt * 8 + q) * 73 + nt * 8 + g]);
                uint32_t b1 = __float_as_uint(Ks[(kt * 8 + q + 4) * 73 + nt * 8 + g]);
                mma_tf32(sc[0][nt], qa[0][kt][0], qa[0][kt][1], qa[0][kt][2], qa[0][kt][3], b0, b1);
                mma_tf32(sc[1][nt], qa[1][kt][0], qa[1][kt][1], qa[1][kt][2], qa[1][kt][3], b0, b1);
            }
        }

        // ---- bias + scale (log2 domain) + chunk max ----
        float mx[2][2] = {{-1e30f, -1e30f}, {-1e30f, -1e30f}};
        #pragma unroll
        for (int mt = 0; mt < 2; mt++) {
            int i0 = I0 + mt * 16 + g;
            #pragma unroll
            for (int nt = 0; nt < 8; nt++) {
                int key = c * 64 + nt * 8 + 2 * q;
                const float* bp = bn + (size_t)key * SS + i0;
                float4 s = sc[mt][nt];
                s.x = fmaf(s.x, SCALE2, bp[0]   * LOG2E);
                s.y = fmaf(s.y, SCALE2, bp[SS]  * LOG2E);
                s.z = fmaf(s.z, SCALE2, bp[8]   * LOG2E);
                s.w = fmaf(s.w, SCALE2, bp[SS + 8] * LOG2E);
                sc[mt][nt] = s;
                mx[mt][0] = fmaxf(mx[mt][0], fmaxf(s.x, s.y));
                mx[mt][1] = fmaxf(mx[mt][1], fmaxf(s.z, s.w));
            }
        }
        #pragma unroll
        for (int mt = 0; mt < 2; mt++)
            #pragma unroll
            for (int h = 0; h < 2; h++) {
                float v = mx[mt][h];
                v = fmaxf(v, __shfl_xor_sync(0xffffffffu, v, 1));
                v = fmaxf(v, __shfl_xor_sync(0xffffffffu, v, 2));
                mx[mt][h] = v;
            }

        float al[2][2], mn[2][2];
        #pragma unroll
        for (int mt = 0; mt < 2; mt++)
            #pragma unroll
            for (int h = 0; h < 2; h++) {
                mn[mt][h] = fmaxf(m_[mt][h], mx[mt][h]);
                al[mt][h] = fexp2(m_[mt][h] - mn[mt][h]);
                m_[mt][h] = mn[mt][h];
            }

        // ---- P = exp2(s - mn), row sums ----
        float rs_[2][2] = {{0.f, 0.f}, {0.f, 0.f}};
        #pragma unroll
        for (int mt = 0; mt < 2; mt++) {
            #pragma unroll
            for (int nt = 0; nt < 8; nt++) {
                float4 s = sc[mt][nt];
                s.x = fexp2(s.x - mn[mt][0]);
                s.y = fexp2(s.y - mn[mt][0]);
                s.z = fexp2(s.z - mn[mt][1]);
                s.w = fexp2(s.w - mn[mt][1]);
                sc[mt][nt] = s;
                rs_[mt][0] += s.x + s.y;
                rs_[mt][1] += s.z + s.w;
            }
        }
        #pragma unroll
        for (int mt = 0; mt < 2; mt++)
            #pragma unroll
            for (int h = 0; h < 2; h++) {
                float v = rs_[mt][h];
                v += __shfl_xor_sync(0xffffffffu, v, 1);
                v += __shfl_xor_sync(0xffffffffu, v, 2);
                l_[mt][h] = fmaf(l_[mt][h], al[mt][h], v);
            }

        // ---- rescale O ----
        #pragma unroll
        for (int mt = 0; mt < 2; mt++)
            #pragma unroll
            for (int nt = 0; nt < 4; nt++) {
                o_[mt][nt].x *= al[mt][0];
                o_[mt][nt].y *= al[mt][0];
                o_[mt][nt].z *= al[mt][1];
                o_[mt][nt].w *= al[mt][1];
            }

        // ---- O += P V : convert P C-frags to A-frags via quad shuffles ----
        #pragma unroll
        for (int kt2 = 0; kt2 < 8; kt2++) {
            uint32_t pa[2][4];
            #pragma unroll
            for (int mt = 0; mt < 2; mt++) {
                float4 pc = sc[mt][kt2];
                float t00 = __shfl_sync(0xffffffffu, pc.x, src0);
                float t01 = __shfl_sync(0xffffffffu, pc.y, src0);
                float t20 = __shfl_sync(0xffffffffu, pc.x, src2);
                float t21 = __shfl_sync(0xffffffffu, pc.y, src2);
                float t10 = __shfl_sync(0xffffffffu, pc.z, src0);
                float t11 = __shfl_sync(0xffffffffu, pc.w, src0);
                float t30 = __shfl_sync(0xffffffffu, pc.z, src2);
                float t31 = __shfl_sync(0xffffffffu, pc.w, src2);
                pa[mt][0] = f2tf32((q & 1) ? t01 : t00);
                pa[mt][1] = f2tf32((q & 1) ? t11 : t10);
                pa[mt][2] = f2tf32((q & 1) ? t21 : t20);
                pa[mt][3] = f2tf32((q & 1) ? t31 : t30);
            }
            #pragma unroll
            for (int nt2 = 0; nt2 < 4; nt2++) {
                uint32_t b0 = __float_as_uint(Vs[(kt2 * 8 + q) * 41 + nt2 * 8 + g]);
                uint32_t b1 = __float_as_uint(Vs[(kt2 * 8 + q + 4) * 41 + nt2 * 8 + g]);
                mma_tf32(o_[0][nt2], pa[0][0], pa[0][1], pa[0][2], pa[0][3], b0, b1);
                mma_tf32(o_[1][nt2], pa[1][0], pa[1][1], pa[1][2], pa[1][3], b0, b1);
            }
        }
    }

    // ---- epilogue: O/l, gate, store ----
    #pragma unroll
    for (int mt = 0; mt < 2; mt++) {
        float i0v = 1.f / l_[mt][0];
        float i1v = 1.f / l_[mt][1];
        size_t r0 = (size_t)(j * SS + I0 + mt * 16 + g) * CC + n * HD;
        size_t r1 = r0 + 8 * CC;
        #pragma unroll
        for (int nt2 = 0; nt2 < 4; nt2++) {
            int col = nt2 * 8 + 2 * q;
            float2 g0 = *(const float2*)(gt + r0 + col);
            float2 g1 = *(const float2*)(gt + r1 + col);
            float4 o4 = o_[mt][nt2];
            *(float2*)(og + r0 + col) = make_float2(o4.x * i0v * g0.x, o4.y * i0v * g0.y);
            *(float2*)(og + r1 + col) = make_float2(o4.z * i1v * g1.x, o4.w * i1v * g1.y);
        }
    }
}

// ---------------- launch -------------------------------------------------------
extern "C" void kernel_launch(void* const* d_in, const int* in_sizes, int n_in,
                              void* d_out, int out_size) {
    const float* pair  = (const float*)d_in[0];
    const float* gamma = (const float*)d_in[1];
    const float* beta  = (const float*)d_in[2];
    const float* Wq    = (const float*)d_in[3];
    const float* Wk    = (const float*)d_in[4];
    const float* Wv    = (const float*)d_in[5];
    const float* Wb    = (const float*)d_in[6];
    const float* Wg    = (const float*)d_in[7];
    const float* bg    = (const float*)d_in[8];
    const float* Wo    = (const float*)d_in[9];
    const float* bo    = (const float*)d_in[10];
    float* out = (float*)d_out;

    float* base = nullptr;
    cudaGetSymbolAddress((void**)&base, g_scratch);
    float* z    = base;
    float* qt   = base + 1 * 8388608;
    float* kt   = base + 2 * 8388608;
    float* vt   = base + 3 * 8388608;
    float* gt   = base + 4 * 8388608;
    float* og   = base + 5 * 8388608;
    float* bias = base + 6 * 8388608;

    const int GEMM_SMEM = (18432 + 4224) * 4;   // 90624 bytes
    cudaFuncSetAttribute(mma_gemm_kernel,
                         cudaFuncAttributeMaxDynamicSharedMemorySize, GEMM_SMEM);

    ln_kernel<<<MTOT / 8, 256>>>(pair, gamma, beta, z);

    GemmArgs pa;
    pa.A = z;
    pa.W[0] = Wq; pa.W[1] = Wk; pa.W[2] = Wv; pa.W[3] = Wg;
    pa.out[0] = qt; pa.out[1] = kt; pa.out[2] = vt; pa.out[3] = gt;
    pa.bias[0] = nullptr; pa.bias[1] = nullptr; pa.bias[2] = nullptr; pa.bias[3] = bg;
    pa.sig[0] = 0; pa.sig[1] = 0; pa.sig[2] = 0; pa.sig[3] = 1;
    pa.nw = 4;
    mma_gemm_kernel<<<MTOT / 128, 256, GEMM_SMEM>>>(pa);

    projb_kernel<<<MTOT / 8, 256>>>(z, Wb, bias);

    attn_mma_kernel<<<dim3(SS, NH), 256>>>(qt, kt, vt, gt, bias, og);

    GemmArgs oa;
    oa.A = og;
    oa.W[0] = Wo;
    oa.out[0] = out;
    oa.bias[0] = bo;
    oa.sig[0] = 0;
    oa.nw = 1;
    mma_gemm_kernel<<<MTOT / 128, 256, GEMM_SMEM>>>(oa);
}

// round 8
// speedup vs baseline: 4.3779x; 1.0833x over previous
#include <cuda_runtime.h>
#include <cuda_bf16.h>
#include <math.h>
#include <stdint.h>

#define SS 256       // sequence
#define CC 128       // channels
#define NH 4
#define HD 32
#define MTOT (SS*SS) // 65536
#define ATT_SCALE 0.17677669529663687f  // 1/sqrt(32)
#define LOG2E 1.4426950408889634f
#define LN_EPS 1e-5f

// ---------------- scratch (no allocation allowed; single big __device__ blob) ---
// layout (floats):
//   z   : [0,            8388608)
//   qt  : [8388608,     16777216)   transposed: row = j*S + i
//   kt  : [16777216,    25165824)
//   vt  : [25165824,    33554432)
//   gt  : [33554432,    41943040)
//   og  : [41943040,    50331648)   gated attention output, row = j*S + i
//   bias_t: [50331648, +4*65536)    [n][k][i]  (pre-scaled by LOG2E)
__device__ float g_scratch[50331648 + NH*MTOT];

__device__ __forceinline__ uint32_t f2tf32(float f) {
    uint32_t r;
    asm("cvt.rna.tf32.f32 %0, %1;" : "=r"(r) : "f"(f));
    return r;
}
__device__ __forceinline__ float tf32f(float f) { return __uint_as_float(f2tf32(f)); }

__device__ __forceinline__ float fexp2(float x) {
    float r;
    asm("ex2.approx.ftz.f32 %0, %1;" : "=f"(r) : "f"(x));
    return r;
}

// pack two fp32 -> f16x2 (hi in upper 16 bits, lo in lower) — same operand
// convention as the (empirically validated) bf16x2 pack used previously.
__device__ __forceinline__ uint32_t f16x2(float hi, float lo) {
    uint32_t r;
    asm("cvt.rn.f16x2.f32 %0, %1, %2;" : "=r"(r) : "f"(hi), "f"(lo));
    return r;
}

__device__ __forceinline__ void mma_tf32(float4& c, uint32_t a0, uint32_t a1,
                                         uint32_t a2, uint32_t a3,
                                         uint32_t b0, uint32_t b1) {
    asm volatile(
        "mma.sync.aligned.m16n8k8.row.col.f32.tf32.tf32.f32 "
        "{%0,%1,%2,%3}, {%4,%5,%6,%7}, {%8,%9}, {%0,%1,%2,%3};"
        : "+f"(c.x), "+f"(c.y), "+f"(c.z), "+f"(c.w)
        : "r"(a0), "r"(a1), "r"(a2), "r"(a3), "r"(b0), "r"(b1));
}

__device__ __forceinline__ void mma_f16(float4& c, uint32_t a0, uint32_t a1,
                                        uint32_t a2, uint32_t a3,
                                        uint32_t b0, uint32_t b1) {
    asm volatile(
        "mma.sync.aligned.m16n8k16.row.col.f32.f16.f16.f32 "
        "{%0,%1,%2,%3}, {%4,%5,%6,%7}, {%8,%9}, {%0,%1,%2,%3};"
        : "+f"(c.x), "+f"(c.y), "+f"(c.z), "+f"(c.w)
        : "r"(a0), "r"(a1), "r"(a2), "r"(a3), "r"(b0), "r"(b1));
}

// ---------------- LayerNorm: one warp per row of 128 channels -------------------
__global__ void ln_kernel(const float* __restrict__ x, const float* __restrict__ gamma,
                          const float* __restrict__ beta, float* __restrict__ z) {
    int warp = blockIdx.x * 8 + (threadIdx.x >> 5);
    int lane = threadIdx.x & 31;
    if (warp >= MTOT) return;
    const float4 v = ((const float4*)(x + (size_t)warp * CC))[lane];
    float s  = v.x + v.y + v.z + v.w;
    float sq = v.x*v.x + v.y*v.y + v.z*v.z + v.w*v.w;
    #pragma unroll
    for (int off = 16; off; off >>= 1) {
        s  += __shfl_xor_sync(0xffffffffu, s,  off);
        sq += __shfl_xor_sync(0xffffffffu, sq, off);
    }
    float mu  = s * (1.0f / CC);
    float var = sq * (1.0f / CC) - mu * mu;
    float rs  = rsqrtf(var + LN_EPS);
    const float4 g4 = ((const float4*)gamma)[lane];
    const float4 b4 = ((const float4*)beta)[lane];
    float4 o;
    o.x = (v.x - mu) * rs * g4.x + b4.x;
    o.y = (v.y - mu) * rs * g4.y + b4.y;
    o.z = (v.z - mu) * rs * g4.z + b4.z;
    o.w = (v.w - mu) * rs * g4.w + b4.w;
    ((float4*)(z + (size_t)warp * CC))[lane] = o;
}

// ---------------- tf32 MMA GEMM: [65536,128] x (up to 4x) [128,128] ------------
struct GemmArgs {
    const float* A;
    const float* W[4];
    float*       out[4];
    const float* bias[4];
    int          sig[4];
    int          nw;
};

__global__ void __launch_bounds__(256, 2)
mma_gemm_kernel(GemmArgs ga) {
    extern __shared__ float sm[];
    float* As = sm;                  // 4 * 128 * 36 = 18432 floats
    float* Bs = sm + 18432;          // 32 * 132 = 4224 floats
    const int t = threadIdx.x;
    const int lane = t & 31, warp = t >> 5;
    const int wm = warp & 3, wn = warp >> 2;
    const int m0w = wm * 32, n0w = wn * 64;
    const int g = lane >> 2, q = lane & 3;
    const int row0 = blockIdx.x * 128;

    #pragma unroll
    for (int i = 0; i < 16; i++) {
        int id = t + i * 256;
        int r = id >> 5, c4g = id & 31;
        float4 v = ((const float4*)ga.A)[(size_t)(row0 + r) * 32 + c4g];
        int kc = c4g >> 3, c4 = c4g & 7;
        float* dst = As + kc * 4608 + r * 36 + c4;
        dst[0]  = tf32f(v.x);
        dst[8]  = tf32f(v.y);
        dst[16] = tf32f(v.z);
        dst[24] = tf32f(v.w);
    }

    const float4* As4 = (const float4*)As;
    const int abase0 = (m0w + g) * 9 + 2 * q;   // float4 units

    for (int w = 0; w < ga.nw; w++) {
        float4 acc[2][8];
        #pragma unroll
        for (int mt = 0; mt < 2; mt++)
            #pragma unroll
            for (int nt = 0; nt < 8; nt++) acc[mt][nt] = make_float4(0.f, 0.f, 0.f, 0.f);

        const float* W = ga.W[w];
        for (int kc = 0; kc < 4; kc++) {
            __syncthreads();
            #pragma unroll
            for (int i = 0; i < 4; i++) {
                int id = t + i * 256;
                int kk = id >> 5, n4 = id & 31;
                float4 v = ((const float4*)W)[(size_t)(kc * 32 + kk) * 32 + n4];
                float4 o;
                o.x = tf32f(v.x); o.y = tf32f(v.y); o.z = tf32f(v.z); o.w = tf32f(v.w);
                ((float4*)Bs)[kk * 33 + n4] = o;
            }
            __syncthreads();

            const int abase = kc * 1152 + abase0;
            #pragma unroll
            for (int tp = 0; tp < 2; tp++) {
                float4 alo[2], ahi[2];
                #pragma unroll
                for (int mt = 0; mt < 2; mt++) {
                    alo[mt] = As4[abase + mt * 144 + tp];
                    ahi[mt] = As4[abase + mt * 144 + 72 + tp];
                }
                #pragma unroll
                for (int th = 0; th < 2; th++) {
                    const int krow = (tp * 2 + th) * 8 + q;
                    uint32_t a0[2], a1[2], a2[2], a3[2];
                    #pragma unroll
                    for (int mt = 0; mt < 2; mt++) {
                        a0[mt] = __float_as_uint(th ? alo[mt].z : alo[mt].x);
                        a2[mt] = __float_as_uint(th ? alo[mt].w : alo[mt].y);
                        a1[mt] = __float_as_uint(th ? ahi[mt].z : ahi[mt].x);
                        a3[mt] = __float_as_uint(th ? ahi[mt].w : ahi[mt].y);
                    }
                    #pragma unroll
                    for (int nt = 0; nt < 8; nt++) {
                        const int cn = n0w + nt * 8 + g;
                        uint32_t b0 = __float_as_uint(Bs[krow * 132 + cn]);
                        uint32_t b1 = __float_as_uint(Bs[(krow + 4) * 132 + cn]);
                        mma_tf32(acc[0][nt], a0[0], a1[0], a2[0], a3[0], b0, b1);
                        mma_tf32(acc[1][nt], a0[1], a1[1], a2[1], a3[1], b0, b1);
                    }
                }
            }
        }

        const float* bias = ga.bias[w];
        const int sig = ga.sig[w];
        float* out = ga.out[w];
        float2 bv[8];
        #pragma unroll
        for (int nt = 0; nt < 8; nt++) {
            if (bias) bv[nt] = *(const float2*)(bias + n0w + nt * 8 + 2 * q);
            else      bv[nt] = make_float2(0.f, 0.f);
        }
        #pragma unroll
        for (int mt = 0; mt < 2; mt++) {
            int r  = row0 + m0w + mt * 16 + g;
            int r2 = r + 8;
            int or0 = ((r  & 255) << 8) | (r  >> 8);
            int or1 = ((r2 & 255) << 8) | (r2 >> 8);
            #pragma unroll
            for (int nt = 0; nt < 8; nt++) {
                int col = n0w + nt * 8 + 2 * q;
                float4 c = acc[mt][nt];
                float v0 = c.x + bv[nt].x, v1 = c.y + bv[nt].y;
                float v2 = c.z + bv[nt].x, v3 = c.w + bv[nt].y;
                if (sig) {
                    v0 = 1.0f / (1.0f + __expf(-v0));
                    v1 = 1.0f / (1.0f + __expf(-v1));
                    v2 = 1.0f / (1.0f + __expf(-v2));
                    v3 = 1.0f / (1.0f + __expf(-v3));
                }
                *(float2*)(out + (size_t)or0 * CC + col) = make_float2(v0, v1);
                *(float2*)(out + (size_t)or1 * CC + col) = make_float2(v2, v3);
            }
        }
    }
}

// ---------------- attention bias projection: z @ Wb -> bias_t[n][k][i] ---------
// NOTE: stores bias * LOG2E (attention softmax runs in log2 domain).
__global__ void projb_kernel(const float* __restrict__ z, const float* __restrict__ Wb,
                             float* __restrict__ bias_t) {
    int warp = blockIdx.x * 8 + (threadIdx.x >> 5);
    int lane = threadIdx.x & 31;
    if (warp >= MTOT) return;
    const float4 v = ((const float4*)(z + (size_t)warp * CC))[lane];
    float p0 = 0, p1 = 0, p2 = 0, p3 = 0;
    const float zc[4] = {v.x, v.y, v.z, v.w};
    #pragma unroll
    for (int qq = 0; qq < 4; qq++) {
        int c = lane * 4 + qq;
        p0 += zc[qq] * Wb[c * 4 + 0];
        p1 += zc[qq] * Wb[c * 4 + 1];
        p2 += zc[qq] * Wb[c * 4 + 2];
        p3 += zc[qq] * Wb[c * 4 + 3];
    }
    #pragma unroll
    for (int off = 16; off; off >>= 1) {
        p0 += __shfl_xor_sync(0xffffffffu, p0, off);
        p1 += __shfl_xor_sync(0xffffffffu, p1, off);
        p2 += __shfl_xor_sync(0xffffffffu, p2, off);
        p3 += __shfl_xor_sync(0xffffffffu, p3, off);
    }
    if (lane == 0) {
        int o = (warp & (SS - 1)) * SS + (warp >> 8);
        bias_t[0 * MTOT + o] = p0 * LOG2E;
        bias_t[1 * MTOT + o] = p1 * LOG2E;
        bias_t[2 * MTOT + o] = p2 * LOG2E;
        bias_t[3 * MTOT + o] = p3 * LOG2E;
    }
}

// ---------------- tf32/fp16 MMA flash attention: one block per (j, head n) -----
// 8 warps; warp w owns query rows [32w, 32w+32). Keys in 4 chunks of 64.
// smem (dynamic, floats):
//   Ks   [0,    2336)  : K tf32, [d=32][key], stride 73 (conflict-free)
//   Vh   [2336, 3616)  : V f16x2 key-pairs, [kp=32][d=32], stride 40 (c-free)
//   Bss  [3616, 20256) : bias slab [key=64][i=256], stride 260 (c-free)
// S = QK^T in tf32 mma; P packed to fp16 (C-frag == f16 A-frag layout, zero
// shuffles); O += P V via mma.m16n8k16.f16. Softmax in log2 domain.
#define ATT_SMEM_FLOATS 20256
__global__ void __launch_bounds__(256, 1)
attn_mma_kernel(const float* __restrict__ qt, const float* __restrict__ kt,
                const float* __restrict__ vt, const float* __restrict__ gt,
                const float* __restrict__ bias_t, float* __restrict__ og) {
    extern __shared__ float asm_[];
    float*    Ks  = asm_;
    uint32_t* Vh  = (uint32_t*)(asm_ + 2336);
    float*    Bss = asm_ + 3616;

    const int j = blockIdx.x, n = blockIdx.y;
    const int t = threadIdx.x;
    const int lane = t & 31, w = t >> 5;
    const int g = lane >> 2, q = lane & 3;
    const int I0 = w * 32;
    const float SCALE2 = ATT_SCALE * LOG2E;

    // ---- Q fragments (tf32), rows I0+16mt+g (+8), cols 8kt+q (+4) ----
    uint32_t qa[2][4][4];
    #pragma unroll
    for (int mt = 0; mt < 2; mt++) {
        const float* qp0 = qt + (size_t)(j * SS + I0 + mt * 16 + g) * CC + n * HD;
        const float* qp1 = qp0 + 8 * CC;
        #pragma unroll
        for (int kt2 = 0; kt2 < 4; kt2++) {
            qa[mt][kt2][0] = f2tf32(qp0[kt2 * 8 + q]);
            qa[mt][kt2][1] = f2tf32(qp1[kt2 * 8 + q]);
            qa[mt][kt2][2] = f2tf32(qp0[kt2 * 8 + q + 4]);
            qa[mt][kt2][3] = f2tf32(qp1[kt2 * 8 + q + 4]);
        }
    }

    float m_[2][2], l_[2][2];
    float4 o_[2][4];
    #pragma unroll
    for (int mt = 0; mt < 2; mt++) {
        m_[mt][0] = m_[mt][1] = -1e30f;
        l_[mt][0] = l_[mt][1] = 0.f;
        #pragma unroll
        for (int nt = 0; nt < 4; nt++) o_[mt][nt] = make_float4(0.f, 0.f, 0.f, 0.f);
    }

    const float* bn = bias_t + (size_t)n * MTOT;

    for (int c = 0; c < 4; c++) {
        __syncthreads();
        // ---- stage K (tf32, [d][key] stride 73) ----
        #pragma unroll
        for (int i = 0; i < 2; i++) {
            int id = t + i * 256;             // 0..511
            int key = id >> 3, c4 = id & 7;
            size_t src = (size_t)(j * SS + c * 64 + key) * CC + n * HD + c4 * 4;
            float4 kv = *(const float4*)(kt + src);
            Ks[(c4 * 4 + 0) * 73 + key] = tf32f(kv.x);
            Ks[(c4 * 4 + 1) * 73 + key] = tf32f(kv.y);
            Ks[(c4 * 4 + 2) * 73 + key] = tf32f(kv.z);
            Ks[(c4 * 4 + 3) * 73 + key] = tf32f(kv.w);
        }
        // ---- stage V (fp16 key-pairs, [kp][d] stride 40) ----
        {
            int kp = t >> 3, c4 = t & 7;
            size_t s0 = (size_t)(j * SS + c * 64 + 2 * kp) * CC + n * HD + c4 * 4;
            float4 v0 = *(const float4*)(vt + s0);
            float4 v1 = *(const float4*)(vt + s0 + CC);
            uint32_t* vd = Vh + kp * 40 + c4 * 4;
            vd[0] = f16x2(v1.x, v0.x);
            vd[1] = f16x2(v1.y, v0.y);
            vd[2] = f16x2(v1.z, v0.z);
            vd[3] = f16x2(v1.w, v0.w);
        }
        // ---- stage bias slab ([key][i] stride 260, pre-scaled by LOG2E) ----
        #pragma unroll
        for (int i = 0; i < 16; i++) {
            int id = t + i * 256;             // 0..4095
            int key = id >> 6, c4b = id & 63;
            float4 bv = *(const float4*)(bn + (size_t)(c * 64 + key) * SS + c4b * 4);
            *(float4*)(Bss + key * 260 + c4b * 4) = bv;
        }
        __syncthreads();

        // ---- S = Q K^T (tf32) ----
        float4 sc[2][8];
        #pragma unroll
        for (int mt = 0; mt < 2; mt++)
            #pragma unroll
            for (int nt = 0; nt < 8; nt++) sc[mt][nt] = make_float4(0.f, 0.f, 0.f, 0.f);
        #pragma unroll
        for (int nt = 0; nt < 8; nt++) {
            #pragma unroll
            for (int kt2 = 0; kt2 < 4; kt2++) {
                uint32_t b0 = __float_as_uint(Ks[(kt2 * 8 + q) * 73 + nt * 8 + g]);
                uint32_t b1 = __float_as_uint(Ks[(kt2 * 8 + q + 4) * 73 + nt * 8 + g]);
                mma_tf32(sc[0][nt], qa[0][kt2][0], qa[0][kt2][1], qa[0][kt2][2], qa[0][kt2][3], b0, b1);
                mma_tf32(sc[1][nt], qa[1][kt2][0], qa[1][kt2][1], qa[1][kt2][2], qa[1][kt2][3], b0, b1);
            }
        }

        // ---- bias add (smem) + chunk max ----
        float mx[2][2] = {{-1e30f, -1e30f}, {-1e30f, -1e30f}};
        #pragma unroll
        for (int mt = 0; mt < 2; mt++) {
            int i0 = I0 + mt * 16 + g;
            #pragma unroll
            for (int nt = 0; nt < 8; nt++) {
                int kl = nt * 8 + 2 * q;
                const float* b0p = Bss + kl * 260 + i0;
                const float* b1p = b0p + 260;
                float4 s = sc[mt][nt];
                s.x = fmaf(s.x, SCALE2, b0p[0]);
                s.y = fmaf(s.y, SCALE2, b1p[0]);
                s.z = fmaf(s.z, SCALE2, b0p[8]);
                s.w = fmaf(s.w, SCALE2, b1p[8]);
                sc[mt][nt] = s;
                mx[mt][0] = fmaxf(mx[mt][0], fmaxf(s.x, s.y));
                mx[mt][1] = fmaxf(mx[mt][1], fmaxf(s.z, s.w));
            }
        }
        #pragma unroll
        for (int mt = 0; mt < 2; mt++)
            #pragma unroll
            for (int h = 0; h < 2; h++) {
                float v = mx[mt][h];
                v = fmaxf(v, __shfl_xor_sync(0xffffffffu, v, 1));
                v = fmaxf(v, __shfl_xor_sync(0xffffffffu, v, 2));
                mx[mt][h] = v;
            }

        float al[2][2], mn[2][2];
        #pragma unroll
        for (int mt = 0; mt < 2; mt++)
            #pragma unroll
            for (int h = 0; h < 2; h++) {
                mn[mt][h] = fmaxf(m_[mt][h], mx[mt][h]);
                al[mt][h] = fexp2(m_[mt][h] - mn[mt][h]);
                m_[mt][h] = mn[mt][h];
            }

        // ---- P = exp2(s - mn), row sums ----
        float rs_[2][2] = {{0.f, 0.f}, {0.f, 0.f}};
        #pragma unroll
        for (int mt = 0; mt < 2; mt++) {
            #pragma unroll
            for (int nt = 0; nt < 8; nt++) {
                float4 s = sc[mt][nt];
                s.x = fexp2(s.x - mn[mt][0]);
                s.y = fexp2(s.y - mn[mt][0]);
                s.z = fexp2(s.z - mn[mt][1]);
                s.w = fexp2(s.w - mn[mt][1]);
                sc[mt][nt] = s;
                rs_[mt][0] += s.x + s.y;
                rs_[mt][1] += s.z + s.w;
            }
        }
        #pragma unroll
        for (int mt = 0; mt < 2; mt++)
            #pragma unroll
            for (int h = 0; h < 2; h++) {
                float v = rs_[mt][h];
                v += __shfl_xor_sync(0xffffffffu, v, 1);
                v += __shfl_xor_sync(0xffffffffu, v, 2);
                l_[mt][h] = fmaf(l_[mt][h], al[mt][h], v);
            }

        // ---- rescale O ----
        #pragma unroll
        for (int mt = 0; mt < 2; mt++)
            #pragma unroll
            for (int nt = 0; nt < 4; nt++) {
                o_[mt][nt].x *= al[mt][0];
                o_[mt][nt].y *= al[mt][0];
                o_[mt][nt].z *= al[mt][1];
                o_[mt][nt].w *= al[mt][1];
            }

        // ---- O += P V : pack P C-frags directly into f16 A-frags ----
        #pragma unroll
        for (int kt2 = 0; kt2 < 4; kt2++) {
            uint32_t pa[2][4];
            #pragma unroll
            for (int mt = 0; mt < 2; mt++) {
                float4 p0 = sc[mt][2 * kt2];
                float4 p1 = sc[mt][2 * kt2 + 1];
                pa[mt][0] = f16x2(p0.y, p0.x);   // row g,   k 16kt2+2q,+1
                pa[mt][1] = f16x2(p0.w, p0.z);   // row g+8
                pa[mt][2] = f16x2(p1.y, p1.x);   // row g,   k 16kt2+8+2q,+1
                pa[mt][3] = f16x2(p1.w, p1.z);   // row g+8
            }
            #pragma unroll
            for (int nt2 = 0; nt2 < 4; nt2++) {
                uint32_t b0 = Vh[(kt2 * 8 + q) * 40 + nt2 * 8 + g];
                uint32_t b1 = Vh[(kt2 * 8 + q + 4) * 40 + nt2 * 8 + g];
                mma_f16(o_[0][nt2], pa[0][0], pa[0][1], pa[0][2], pa[0][3], b0, b1);
                mma_f16(o_[1][nt2], pa[1][0], pa[1][1], pa[1][2], pa[1][3], b0, b1);
            }
        }
    }

    // ---- epilogue: O/l, gate, store ----
    #pragma unroll
    for (int mt = 0; mt < 2; mt++) {
        float i0v = 1.f / l_[mt][0];
        float i1v = 1.f / l_[mt][1];
        size_t r0 = (size_t)(j * SS + I0 + mt * 16 + g) * CC + n * HD;
        size_t r1 = r0 + 8 * CC;
        #pragma unroll
        for (int nt2 = 0; nt2 < 4; nt2++) {
            int col = nt2 * 8 + 2 * q;
            float2 g0 = *(const float2*)(gt + r0 + col);
            float2 g1 = *(const float2*)(gt + r1 + col);
            float4 o4 = o_[mt][nt2];
            *(float2*)(og + r0 + col) = make_float2(o4.x * i0v * g0.x, o4.y * i0v * g0.y);
            *(float2*)(og + r1 + col) = make_float2(o4.z * i1v * g1.x, o4.w * i1v * g1.y);
        }
    }
}

// ---------------- launch -------------------------------------------------------
extern "C" void kernel_launch(void* const* d_in, const int* in_sizes, int n_in,
                              void* d_out, int out_size) {
    const float* pair  = (const float*)d_in[0];
    const float* gamma = (const float*)d_in[1];
    const float* beta  = (const float*)d_in[2];
    const float* Wq    = (const float*)d_in[3];
    const float* Wk    = (const float*)d_in[4];
    const float* Wv    = (const float*)d_in[5];
    const float* Wb    = (const float*)d_in[6];
    const float* Wg    = (const float*)d_in[7];
    const float* bg    = (const float*)d_in[8];
    const float* Wo    = (const float*)d_in[9];
    const float* bo    = (const float*)d_in[10];
    float* out = (float*)d_out;

    float* base = nullptr;
    cudaGetSymbolAddress((void**)&base, g_scratch);
    float* z    = base;
    float* qt   = base + 1 * 8388608;
    float* kt   = base + 2 * 8388608;
    float* vt   = base + 3 * 8388608;
    float* gt   = base + 4 * 8388608;
    float* og   = base + 5 * 8388608;
    float* bias = base + 6 * 8388608;

    const int GEMM_SMEM = (18432 + 4224) * 4;     // 90624 bytes
    const int ATT_SMEM  = ATT_SMEM_FLOATS * 4;    // 81024 bytes
    cudaFuncSetAttribute(mma_gemm_kernel,
                         cudaFuncAttributeMaxDynamicSharedMemorySize, GEMM_SMEM);
    cudaFuncSetAttribute(attn_mma_kernel,
                         cudaFuncAttributeMaxDynamicSharedMemorySize, ATT_SMEM);

    ln_kernel<<<MTOT / 8, 256>>>(pair, gamma, beta, z);

    GemmArgs pa;
    pa.A = z;
    pa.W[0] = Wq; pa.W[1] = Wk; pa.W[2] = Wv; pa.W[3] = Wg;
    pa.out[0] = qt; pa.out[1] = kt; pa.out[2] = vt; pa.out[3] = gt;
    pa.bias[0] = nullptr; pa.bias[1] = nullptr; pa.bias[2] = nullptr; pa.bias[3] = bg;
    pa.sig[0] = 0; pa.sig[1] = 0; pa.sig[2] = 0; pa.sig[3] = 1;
    pa.nw = 4;
    mma_gemm_kernel<<<MTOT / 128, 256, GEMM_SMEM>>>(pa);

    projb_kernel<<<MTOT / 8, 256>>>(z, Wb, bias);

    attn_mma_kernel<<<dim3(SS, NH), 256, ATT_SMEM>>>(qt, kt, vt, gt, bias, og);

    GemmArgs oa;
    oa.A = og;
    oa.W[0] = Wo;
    oa.out[0] = out;
    oa.bias[0] = bo;
    oa.sig[0] = 0;
    oa.nw = 1;
    mma_gemm_kernel<<<MTOT / 128, 256, GEMM_SMEM>>>(oa);
}

// round 9
// speedup vs baseline: 5.2412x; 1.1972x over previous
#include <cuda_runtime.h>
#include <cuda_bf16.h>
#include <cuda_fp16.h>
#include <math.h>
#include <stdint.h>

#define SS 256       // sequence
#define CC 128       // channels
#define NH 4
#define HD 32
#define MTOT (SS*SS) // 65536
#define ATT_SCALE 0.17677669529663687f  // 1/sqrt(32)
#define LOG2E 1.4426950408889634f
#define LN_EPS 1e-5f

// ---------------- scratch (no allocation allowed; single big __device__ blob) ---
// layout (floats):
//   z   : [0,            8388608)
//   qt  : [8388608,     16777216)   transposed: row = j*S + i
//   kt  : [16777216,    25165824)
//   vt  : [25165824,    33554432)
//   gt  : [33554432,    41943040)
//   og  : [41943040,    50331648)   gated attention output, row = j*S + i
//   bias_t: [50331648, +4*65536)    [n][k][i]  (pre-scaled by LOG2E)
__device__ float g_scratch[50331648 + NH*MTOT];

__device__ __forceinline__ uint32_t f2tf32(float f) {
    uint32_t r;
    asm("cvt.rna.tf32.f32 %0, %1;" : "=r"(r) : "f"(f));
    return r;
}
__device__ __forceinline__ float tf32f(float f) { return __uint_as_float(f2tf32(f)); }

__device__ __forceinline__ float fexp2(float x) {
    float r;
    asm("ex2.approx.ftz.f32 %0, %1;" : "=f"(r) : "f"(x));
    return r;
}

// pack two fp32 -> f16x2 (lo = second operand) — empirically validated in R8.
__device__ __forceinline__ uint32_t f16x2(float hi, float lo) {
    uint32_t r;
    asm("cvt.rn.f16x2.f32 %0, %1, %2;" : "=r"(r) : "f"(hi), "f"(lo));
    return r;
}

__device__ __forceinline__ void mma_tf32(float4& c, uint32_t a0, uint32_t a1,
                                         uint32_t a2, uint32_t a3,
                                         uint32_t b0, uint32_t b1) {
    asm volatile(
        "mma.sync.aligned.m16n8k8.row.col.f32.tf32.tf32.f32 "
        "{%0,%1,%2,%3}, {%4,%5,%6,%7}, {%8,%9}, {%0,%1,%2,%3};"
        : "+f"(c.x), "+f"(c.y), "+f"(c.z), "+f"(c.w)
        : "r"(a0), "r"(a1), "r"(a2), "r"(a3), "r"(b0), "r"(b1));
}

__device__ __forceinline__ void mma_f16(float4& c, uint32_t a0, uint32_t a1,
                                        uint32_t a2, uint32_t a3,
                                        uint32_t b0, uint32_t b1) {
    asm volatile(
        "mma.sync.aligned.m16n8k16.row.col.f32.f16.f16.f32 "
        "{%0,%1,%2,%3}, {%4,%5,%6,%7}, {%8,%9}, {%0,%1,%2,%3};"
        : "+f"(c.x), "+f"(c.y), "+f"(c.z), "+f"(c.w)
        : "r"(a0), "r"(a1), "r"(a2), "r"(a3), "r"(b0), "r"(b1));
}

#define LDSM_X4(d0,d1,d2,d3,a) \
    asm volatile("ldmatrix.sync.aligned.m8n8.x4.shared.b16 {%0,%1,%2,%3}, [%4];" \
                 : "=r"(d0),"=r"(d1),"=r"(d2),"=r"(d3) : "r"(a))
#define LDSM_X4_T(d0,d1,d2,d3,a) \
    asm volatile("ldmatrix.sync.aligned.m8n8.x4.trans.shared.b16 {%0,%1,%2,%3}, [%4];" \
                 : "=r"(d0),"=r"(d1),"=r"(d2),"=r"(d3) : "r"(a))

// ---------------- LayerNorm: one warp per row of 128 channels -------------------
__global__ void ln_kernel(const float* __restrict__ x, const float* __restrict__ gamma,
                          const float* __restrict__ beta, float* __restrict__ z) {
    int warp = blockIdx.x * 8 + (threadIdx.x >> 5);
    int lane = threadIdx.x & 31;
    if (warp >= MTOT) return;
    const float4 v = ((const float4*)(x + (size_t)warp * CC))[lane];
    float s  = v.x + v.y + v.z + v.w;
    float sq = v.x*v.x + v.y*v.y + v.z*v.z + v.w*v.w;
    #pragma unroll
    for (int off = 16; off; off >>= 1) {
        s  += __shfl_xor_sync(0xffffffffu, s,  off);
        sq += __shfl_xor_sync(0xffffffffu, sq, off);
    }
    float mu  = s * (1.0f / CC);
    float var = sq * (1.0f / CC) - mu * mu;
    float rs  = rsqrtf(var + LN_EPS);
    const float4 g4 = ((const float4*)gamma)[lane];
    const float4 b4 = ((const float4*)beta)[lane];
    float4 o;
    o.x = (v.x - mu) * rs * g4.x + b4.x;
    o.y = (v.y - mu) * rs * g4.y + b4.y;
    o.z = (v.z - mu) * rs * g4.z + b4.z;
    o.w = (v.w - mu) * rs * g4.w + b4.w;
    ((float4*)(z + (size_t)warp * CC))[lane] = o;
}

// ---------------- fp16 MMA GEMM: [65536,128] x (up to 4x) [128,128] ------------
// One block = 128 rows. A staged once as fp16 [m][k] (stride 136 halves); each
// weight staged fp16 [k][n] (stride 136), double-buffered: W(w+1) staged before
// computing w. Fragments via ldmatrix / ldmatrix.trans. fp32 accumulate.
// Writes with transposed spatial index: row R -> (R & 255)*256 + (R >> 8).
struct GemmArgs {
    const float* A;
    const float* W[4];
    float*       out[4];
    const float* bias[4];
    int          sig[4];
    int          nw;
};

#define HGEMM_SMEM (3 * 17408 * 2)   // 104448 bytes

__global__ void __launch_bounds__(256, 2)
hgemm_kernel(GemmArgs ga) {
    extern __shared__ __half hsm[];
    __half* Ah = hsm;                 // 128 * 136
    __half* Bbuf0 = hsm + 17408;
    __half* Bbuf1 = hsm + 34816;
    const int t = threadIdx.x;
    const int lane = t & 31, warp = t >> 5;
    const int wm = warp & 3, wn = warp >> 2;   // 4 (M) x 2 (N)
    const int m0w = wm * 32, n0w = wn * 64;
    const int g = lane >> 2, q = lane & 3;
    const int row0 = blockIdx.x * 128;

    // ---- stage A (fp16, [m][k] stride 136 halves) ----
    #pragma unroll
    for (int i = 0; i < 16; i++) {
        int id = t + i * 256;
        int r = id >> 5, c = id & 31;
        float4 v = ((const float4*)ga.A)[(size_t)(row0 + r) * 32 + c];
        uint2 p;
        p.x = f16x2(v.y, v.x);
        p.y = f16x2(v.w, v.z);
        *(uint2*)(Ah + r * 136 + c * 4) = p;
    }
    // ---- stage W[0] ----
    {
        const float* W = ga.W[0];
        #pragma unroll
        for (int i = 0; i < 16; i++) {
            int id = t + i * 256;
            int kk = id >> 5, n4 = id & 31;
            float4 v = ((const float4*)W)[(size_t)kk * 32 + n4];
            uint2 p;
            p.x = f16x2(v.y, v.x);
            p.y = f16x2(v.w, v.z);
            *(uint2*)(Bbuf0 + kk * 136 + n4 * 4) = p;
        }
    }
    __syncthreads();

    // ldmatrix lane base addresses (bytes)
    uint32_t aBase[2];
    #pragma unroll
    for (int mt = 0; mt < 2; mt++)
        aBase[mt] = (uint32_t)__cvta_generic_to_shared(
            Ah + (m0w + 16 * mt + (lane & 15)) * 136 + (lane >> 4) * 8);
    const int krow_l = (lane & 7) + (((lane & 15) >> 3) << 3);
    const int ncol_l = (lane >> 4) * 8;
    uint32_t bBase[2];
    bBase[0] = (uint32_t)__cvta_generic_to_shared(Bbuf0 + krow_l * 136 + n0w + ncol_l);
    bBase[1] = (uint32_t)__cvta_generic_to_shared(Bbuf1 + krow_l * 136 + n0w + ncol_l);

    for (int w = 0; w < ga.nw; w++) {
        // prefetch next weight into the other buffer (readers of that buffer
        // finished at the __syncthreads ending iteration w-1)
        if (w + 1 < ga.nw) {
            __half* Bn = ((w + 1) & 1) ? Bbuf1 : Bbuf0;
            const float* W = ga.W[w + 1];
            #pragma unroll
            for (int i = 0; i < 16; i++) {
                int id = t + i * 256;
                int kk = id >> 5, n4 = id & 31;
                float4 v = ((const float4*)W)[(size_t)kk * 32 + n4];
                uint2 p;
                p.x = f16x2(v.y, v.x);
                p.y = f16x2(v.w, v.z);
                *(uint2*)(Bn + kk * 136 + n4 * 4) = p;
            }
        }

        float4 acc[2][8];
        #pragma unroll
        for (int mt = 0; mt < 2; mt++)
            #pragma unroll
            for (int nt = 0; nt < 8; nt++) acc[mt][nt] = make_float4(0.f, 0.f, 0.f, 0.f);

        const uint32_t bB = bBase[w & 1];
        #pragma unroll
        for (int step = 0; step < 8; step++) {
            uint32_t a0[4], a1[4];
            LDSM_X4(a0[0], a0[1], a0[2], a0[3], aBase[0] + step * 32);
            LDSM_X4(a1[0], a1[1], a1[2], a1[3], aBase[1] + step * 32);
            #pragma unroll
            for (int p2 = 0; p2 < 4; p2++) {
                uint32_t b0, b1, b2, b3;
                LDSM_X4_T(b0, b1, b2, b3, bB + (step * 2176 + p2 * 16) * 2);
                mma_f16(acc[0][2*p2],   a0[0], a0[1], a0[2], a0[3], b0, b1);
                mma_f16(acc[0][2*p2+1], a0[0], a0[1], a0[2], a0[3], b2, b3);
                mma_f16(acc[1][2*p2],   a1[0], a1[1], a1[2], a1[3], b0, b1);
                mma_f16(acc[1][2*p2+1], a1[0], a1[1], a1[2], a1[3], b2, b3);
            }
        }

        // ---- epilogue ----
        const float* bias = ga.bias[w];
        const int sig = ga.sig[w];
        float* out = ga.out[w];
        float2 bv[8];
        #pragma unroll
        for (int nt = 0; nt < 8; nt++) {
            if (bias) bv[nt] = *(const float2*)(bias + n0w + nt * 8 + 2 * q);
            else      bv[nt] = make_float2(0.f, 0.f);
        }
        #pragma unroll
        for (int mt = 0; mt < 2; mt++) {
            int r  = row0 + m0w + mt * 16 + g;
            int r2 = r + 8;
            int or0 = ((r  & 255) << 8) | (r  >> 8);
            int or1 = ((r2 & 255) << 8) | (r2 >> 8);
            #pragma unroll
            for (int nt = 0; nt < 8; nt++) {
                int col = n0w + nt * 8 + 2 * q;
                float4 c = acc[mt][nt];
                float v0 = c.x + bv[nt].x, v1 = c.y + bv[nt].y;
                float v2 = c.z + bv[nt].x, v3 = c.w + bv[nt].y;
                if (sig) {
                    v0 = 1.0f / (1.0f + __expf(-v0));
                    v1 = 1.0f / (1.0f + __expf(-v1));
                    v2 = 1.0f / (1.0f + __expf(-v2));
                    v3 = 1.0f / (1.0f + __expf(-v3));
                }
                *(float2*)(out + (size_t)or0 * CC + col) = make_float2(v0, v1);
                *(float2*)(out + (size_t)or1 * CC + col) = make_float2(v2, v3);
            }
        }
        __syncthreads();
    }
}

// ---------------- attention bias projection: z @ Wb -> bias_t[n][k][i] ---------
// NOTE: stores bias * LOG2E (attention softmax runs in log2 domain).
__global__ void projb_kernel(const float* __restrict__ z, const float* __restrict__ Wb,
                             float* __restrict__ bias_t) {
    int warp = blockIdx.x * 8 + (threadIdx.x >> 5);
    int lane = threadIdx.x & 31;
    if (warp >= MTOT) return;
    const float4 v = ((const float4*)(z + (size_t)warp * CC))[lane];
    float p0 = 0, p1 = 0, p2 = 0, p3 = 0;
    const float zc[4] = {v.x, v.y, v.z, v.w};
    #pragma unroll
    for (int qq = 0; qq < 4; qq++) {
        int c = lane * 4 + qq;
        p0 += zc[qq] * Wb[c * 4 + 0];
        p1 += zc[qq] * Wb[c * 4 + 1];
        p2 += zc[qq] * Wb[c * 4 + 2];
        p3 += zc[qq] * Wb[c * 4 + 3];
    }
    #pragma unroll
    for (int off = 16; off; off >>= 1) {
        p0 += __shfl_xor_sync(0xffffffffu, p0, off);
        p1 += __shfl_xor_sync(0xffffffffu, p1, off);
        p2 += __shfl_xor_sync(0xffffffffu, p2, off);
        p3 += __shfl_xor_sync(0xffffffffu, p3, off);
    }
    if (lane == 0) {
        int o = (warp & (SS - 1)) * SS + (warp >> 8);
        bias_t[0 * MTOT + o] = p0 * LOG2E;
        bias_t[1 * MTOT + o] = p1 * LOG2E;
        bias_t[2 * MTOT + o] = p2 * LOG2E;
        bias_t[3 * MTOT + o] = p3 * LOG2E;
    }
}

// ---------------- tf32/fp16 MMA flash attention: one block per (j, head n) -----
#define ATT_SMEM_FLOATS 20256
__global__ void __launch_bounds__(256, 1)
attn_mma_kernel(const float* __restrict__ qt, const float* __restrict__ kt,
                const float* __restrict__ vt, const float* __restrict__ gt,
                const float* __restrict__ bias_t, float* __restrict__ og) {
    extern __shared__ float asm_[];
    float*    Ks  = asm_;
    uint32_t* Vh  = (uint32_t*)(asm_ + 2336);
    float*    Bss = asm_ + 3616;

    const int j = blockIdx.x, n = blockIdx.y;
    const int t = threadIdx.x;
    const int lane = t & 31, w = t >> 5;
    const int g = lane >> 2, q = lane & 3;
    const int I0 = w * 32;
    const float SCALE2 = ATT_SCALE * LOG2E;

    uint32_t qa[2][4][4];
    #pragma unroll
    for (int mt = 0; mt < 2; mt++) {
        const float* qp0 = qt + (size_t)(j * SS + I0 + mt * 16 + g) * CC + n * HD;
        const float* qp1 = qp0 + 8 * CC;
        #pragma unroll
        for (int kt2 = 0; kt2 < 4; kt2++) {
            qa[mt][kt2][0] = f2tf32(qp0[kt2 * 8 + q]);
            qa[mt][kt2][1] = f2tf32(qp1[kt2 * 8 + q]);
            qa[mt][kt2][2] = f2tf32(qp0[kt2 * 8 + q + 4]);
            qa[mt][kt2][3] = f2tf32(qp1[kt2 * 8 + q + 4]);
        }
    }

    float m_[2][2], l_[2][2];
    float4 o_[2][4];
    #pragma unroll
    for (int mt = 0; mt < 2; mt++) {
        m_[mt][0] = m_[mt][1] = -1e30f;
        l_[mt][0] = l_[mt][1] = 0.f;
        #pragma unroll
        for (int nt = 0; nt < 4; nt++) o_[mt][nt] = make_float4(0.f, 0.f, 0.f, 0.f);
    }

    const float* bn = bias_t + (size_t)n * MTOT;

    for (int c = 0; c < 4; c++) {
        __syncthreads();
        #pragma unroll
        for (int i = 0; i < 2; i++) {
            int id = t + i * 256;
            int key = id >> 3, c4 = id & 7;
            size_t src = (size_t)(j * SS + c * 64 + key) * CC + n * HD + c4 * 4;
            float4 kv = *(const float4*)(kt + src);
            Ks[(c4 * 4 + 0) * 73 + key] = tf32f(kv.x);
            Ks[(c4 * 4 + 1) * 73 + key] = tf32f(kv.y);
            Ks[(c4 * 4 + 2) * 73 + key] = tf32f(kv.z);
            Ks[(c4 * 4 + 3) * 73 + key] = tf32f(kv.w);
        }
        {
            int kp = t >> 3, c4 = t & 7;
            size_t s0 = (size_t)(j * SS + c * 64 + 2 * kp) * CC + n * HD + c4 * 4;
            float4 v0 = *(const float4*)(vt + s0);
            float4 v1 = *(const float4*)(vt + s0 + CC);
            uint32_t* vd = Vh + kp * 40 + c4 * 4;
            vd[0] = f16x2(v1.x, v0.x);
            vd[1] = f16x2(v1.y, v0.y);
            vd[2] = f16x2(v1.z, v0.z);
            vd[3] = f16x2(v1.w, v0.w);
        }
        #pragma unroll
        for (int i = 0; i < 16; i++) {
            int id = t + i * 256;
            int key = id >> 6, c4b = id & 63;
            float4 bv = *(const float4*)(bn + (size_t)(c * 64 + key) * SS + c4b * 4);
            *(float4*)(Bss + key * 260 + c4b * 4) = bv;
        }
        __syncthreads();

        float4 sc[2][8];
        #pragma unroll
        for (int mt = 0; mt < 2; mt++)
            #pragma unroll
            for (int nt = 0; nt < 8; nt++) sc[mt][nt] = make_float4(0.f, 0.f, 0.f, 0.f);
        #pragma unroll
        for (int nt = 0; nt < 8; nt++) {
            #pragma unroll
            for (int kt2 = 0; kt2 < 4; kt2++) {
                uint32_t b0 = __float_as_uint(Ks[(kt2 * 8 + q) * 73 + nt * 8 + g]);
                uint32_t b1 = __float_as_uint(Ks[(kt2 * 8 + q + 4) * 73 + nt * 8 + g]);
                mma_tf32(sc[0][nt], qa[0][kt2][0], qa[0][kt2][1], qa[0][kt2][2], qa[0][kt2][3], b0, b1);
                mma_tf32(sc[1][nt], qa[1][kt2][0], qa[1][kt2][1], qa[1][kt2][2], qa[1][kt2][3], b0, b1);
            }
        }

        float mx[2][2] = {{-1e30f, -1e30f}, {-1e30f, -1e30f}};
        #pragma unroll
        for (int mt = 0; mt < 2; mt++) {
            int i0 = I0 + mt * 16 + g;
            #pragma unroll
            for (int nt = 0; nt < 8; nt++) {
                int kl = nt * 8 + 2 * q;
                const float* b0p = Bss + kl * 260 + i0;
                const float* b1p = b0p + 260;
                float4 s = sc[mt][nt];
                s.x = fmaf(s.x, SCALE2, b0p[0]);
                s.y = fmaf(s.y, SCALE2, b1p[0]);
                s.z = fmaf(s.z, SCALE2, b0p[8]);
                s.w = fmaf(s.w, SCALE2, b1p[8]);
                sc[mt][nt] = s;
                mx[mt][0] = fmaxf(mx[mt][0], fmaxf(s.x, s.y));
                mx[mt][1] = fmaxf(mx[mt][1], fmaxf(s.z, s.w));
            }
        }
        #pragma unroll
        for (int mt = 0; mt < 2; mt++)
            #pragma unroll
            for (int h = 0; h < 2; h++) {
                float v = mx[mt][h];
                v = fmaxf(v, __shfl_xor_sync(0xffffffffu, v, 1));
                v = fmaxf(v, __shfl_xor_sync(0xffffffffu, v, 2));
                mx[mt][h] = v;
            }

        float al[2][2], mn[2][2];
        #pragma unroll
        for (int mt = 0; mt < 2; mt++)
            #pragma unroll
            for (int h = 0; h < 2; h++) {
                mn[mt][h] = fmaxf(m_[mt][h], mx[mt][h]);
                al[mt][h] = fexp2(m_[mt][h] - mn[mt][h]);
                m_[mt][h] = mn[mt][h];
            }

        float rs_[2][2] = {{0.f, 0.f}, {0.f, 0.f}};
        #pragma unroll
        for (int mt = 0; mt < 2; mt++) {
            #pragma unroll
            for (int nt = 0; nt < 8; nt++) {
                float4 s = sc[mt][nt];
                s.x = fexp2(s.x - mn[mt][0]);
                s.y = fexp2(s.y - mn[mt][0]);
                s.z = fexp2(s.z - mn[mt][1]);
                s.w = fexp2(s.w - mn[mt][1]);
                sc[mt][nt] = s;
                rs_[mt][0] += s.x + s.y;
                rs_[mt][1] += s.z + s.w;
            }
        }
        #pragma unroll
        for (int mt = 0; mt < 2; mt++)
            #pragma unroll
            for (int h = 0; h < 2; h++) {
                float v = rs_[mt][h];
                v += __shfl_xor_sync(0xffffffffu, v, 1);
                v += __shfl_xor_sync(0xffffffffu, v, 2);
                l_[mt][h] = fmaf(l_[mt][h], al[mt][h], v);
            }

        #pragma unroll
        for (int mt = 0; mt < 2; mt++)
            #pragma unroll
            for (int nt = 0; nt < 4; nt++) {
                o_[mt][nt].x *= al[mt][0];
                o_[mt][nt].y *= al[mt][0];
                o_[mt][nt].z *= al[mt][1];
                o_[mt][nt].w *= al[mt][1];
            }

        #pragma unroll
        for (int kt2 = 0; kt2 < 4; kt2++) {
            uint32_t pa[2][4];
            #pragma unroll
            for (int mt = 0; mt < 2; mt++) {
                float4 p0 = sc[mt][2 * kt2];
                float4 p1 = sc[mt][2 * kt2 + 1];
                pa[mt][0] = f16x2(p0.y, p0.x);
                pa[mt][1] = f16x2(p0.w, p0.z);
                pa[mt][2] = f16x2(p1.y, p1.x);
                pa[mt][3] = f16x2(p1.w, p1.z);
            }
            #pragma unroll
            for (int nt2 = 0; nt2 < 4; nt2++) {
                uint32_t b0 = Vh[(kt2 * 8 + q) * 40 + nt2 * 8 + g];
                uint32_t b1 = Vh[(kt2 * 8 + q + 4) * 40 + nt2 * 8 + g];
                mma_f16(o_[0][nt2], pa[0][0], pa[0][1], pa[0][2], pa[0][3], b0, b1);
                mma_f16(o_[1][nt2], pa[1][0], pa[1][1], pa[1][2], pa[1][3], b0, b1);
            }
        }
    }

    #pragma unroll
    for (int mt = 0; mt < 2; mt++) {
        float i0v = 1.f / l_[mt][0];
        float i1v = 1.f / l_[mt][1];
        size_t r0 = (size_t)(j * SS + I0 + mt * 16 + g) * CC + n * HD;
        size_t r1 = r0 + 8 * CC;
        #pragma unroll
        for (int nt2 = 0; nt2 < 4; nt2++) {
            int col = nt2 * 8 + 2 * q;
            float2 g0 = *(const float2*)(gt + r0 + col);
            float2 g1 = *(const float2*)(gt + r1 + col);
            float4 o4 = o_[mt][nt2];
            *(float2*)(og + r0 + col) = make_float2(o4.x * i0v * g0.x, o4.y * i0v * g0.y);
            *(float2*)(og + r1 + col) = make_float2(o4.z * i1v * g1.x, o4.w * i1v * g1.y);
        }
    }
}

// ---------------- launch -------------------------------------------------------
extern "C" void kernel_launch(void* const* d_in, const int* in_sizes, int n_in,
                              void* d_out, int out_size) {
    const float* pair  = (const float*)d_in[0];
    const float* gamma = (const float*)d_in[1];
    const float* beta  = (const float*)d_in[2];
    const float* Wq    = (const float*)d_in[3];
    const float* Wk    = (const float*)d_in[4];
    const float* Wv    = (const float*)d_in[5];
    const float* Wb    = (const float*)d_in[6];
    const float* Wg    = (const float*)d_in[7];
    const float* bg    = (const float*)d_in[8];
    const float* Wo    = (const float*)d_in[9];
    const float* bo    = (const float*)d_in[10];
    float* out = (float*)d_out;

    float* base = nullptr;
    cudaGetSymbolAddress((void**)&base, g_scratch);
    float* z    = base;
    float* qt   = base + 1 * 8388608;
    float* kt   = base + 2 * 8388608;
    float* vt   = base + 3 * 8388608;
    float* gt   = base + 4 * 8388608;
    float* og   = base + 5 * 8388608;
    float* bias = base + 6 * 8388608;

    const int ATT_SMEM = ATT_SMEM_FLOATS * 4;    // 81024 bytes
    cudaFuncSetAttribute(hgemm_kernel,
                         cudaFuncAttributeMaxDynamicSharedMemorySize, HGEMM_SMEM);
    cudaFuncSetAttribute(attn_mma_kernel,
                         cudaFuncAttributeMaxDynamicSharedMemorySize, ATT_SMEM);

    ln_kernel<<<MTOT / 8, 256>>>(pair, gamma, beta, z);

    GemmArgs pa;
    pa.A = z;
    pa.W[0] = Wq; pa.W[1] = Wk; pa.W[2] = Wv; pa.W[3] = Wg;
    pa.out[0] = qt; pa.out[1] = kt; pa.out[2] = vt; pa.out[3] = gt;
    pa.bias[0] = nullptr; pa.bias[1] = nullptr; pa.bias[2] = nullptr; pa.bias[3] = bg;
    pa.sig[0] = 0; pa.sig[1] = 0; pa.sig[2] = 0; pa.sig[3] = 1;
    pa.nw = 4;
    hgemm_kernel<<<MTOT / 128, 256, HGEMM_SMEM>>>(pa);

    projb_kernel<<<MTOT / 8, 256>>>(z, Wb, bias);

    attn_mma_kernel<<<dim3(SS, NH), 256, ATT_SMEM>>>(qt, kt, vt, gt, bias, og);

    GemmArgs oa;
    oa.A = og;
    oa.W[0] = Wo;
    oa.out[0] = out;
    oa.bias[0] = bo;
    oa.sig[0] = 0;
    oa.nw = 1;
    hgemm_kernel<<<MTOT / 128, 256, HGEMM_SMEM>>>(oa);
}